// round 13
// baseline (speedup 1.0000x reference)
#include <cuda_runtime.h>
#include <cuda_fp16.h>
#include <cstdint>

#define N_NODES 262144
#define M_EDGES 1048576
#define F_DIM   64
#define H_DIM   128
#define HEADS   3

// Scratch (static __device__ — no allocations allowed)
// Interleaved node-major fp16 tables: entry (n,h) = 256 halves; chunk l (8 halves
// at offset 8l): [gate[4l..4l+3], msg[4l..4l+3]]
__device__ __half g_self_h[(size_t)HEADS * N_NODES * 256];
__device__ __half g_nbr_h [(size_t)HEADS * N_NODES * 256];
__device__ __half g_acc_h[(size_t)HEADS * N_NODES * 128];  // fp16: sum_e attn*leaky(msg hidden)
__device__ float  g_sattn[(size_t)HEADS * N_NODES];        // sum_e attn
__device__ int    g_rowptr[N_NODES + 1];
// Pre-transposed fp16 W1 weights: [z][n][k], z = h*4 + kind
__device__ __half g_wt[12 * 128 * 64];

__device__ __forceinline__ float lk(float x) { return x >= 0.f ? x : 0.01f * x; }

__device__ __forceinline__ void mma_f16(float* c, const uint32_t* a, const uint32_t* b) {
    asm volatile(
        "mma.sync.aligned.m16n8k16.row.col.f32.f16.f16.f32 "
        "{%0,%1,%2,%3},{%4,%5,%6,%7},{%8,%9},{%0,%1,%2,%3};"
        : "+f"(c[0]), "+f"(c[1]), "+f"(c[2]), "+f"(c[3])
        : "r"(a[0]), "r"(a[1]), "r"(a[2]), "r"(a[3]), "r"(b[0]), "r"(b[1]));
}

// ---------------------------------------------------------------------------
// K0: convert+transpose all 12 W1 matrices to fp16 [n][k] layout, once.
// ---------------------------------------------------------------------------
__global__ void prep_weights_kernel(const float* __restrict__ gate_w1,
                                    const float* __restrict__ msg_w1)
{
    const int z = blockIdx.x;
    const int h = z >> 2;
    const int kind = z & 3;
    const float* W;
    if (kind == 0)      W = gate_w1 + (size_t)h*128*128;
    else if (kind == 1) W = msg_w1  + (size_t)h*128*128;
    else if (kind == 2) W = gate_w1 + (size_t)h*128*128 + 64*128;
    else                W = msg_w1  + (size_t)h*128*128 + 64*128;

    __half* dst = g_wt + (size_t)z * 8192;
    for (int i = threadIdx.x; i < 8192; i += 256) {
        const int n = i >> 6;
        const int k = i & 63;
        dst[i] = __float2half(W[(size_t)k * 128 + n]);
    }
}

// ---------------------------------------------------------------------------
// K1: fused node precompute. One block owns a 128-node X tile; loops over 12
// pre-transposed fp16 weight matrices, double-buffered, fp16 m16n8k16 MMA.
// Epilogue writes INTERLEAVED table layout (gate/msg chunks of 4).
// ---------------------------------------------------------------------------
__global__ void __launch_bounds__(256, 2)
node_gemm_kernel(const float* __restrict__ X,
                 const float* __restrict__ gate_b1,
                 const float* __restrict__ msg_b1)
{
    __shared__ __half As[128][72];       // 128 nodes x 64 k
    __shared__ __half Bst[2][128][72];   // double-buffered: 128 out-cols x 64 k

    const int tid  = threadIdx.x;     // 256 threads, 8 warps
    const int wid  = tid >> 5;
    const int lane = tid & 31;
    const int gid  = lane >> 2;       // 0..7
    const int tig  = lane & 3;        // 0..3
    const int warp_m = wid & 3;       // 4 warps over 128 rows
    const int warp_n = wid >> 2;      // 2 warps over 128 cols (64 each)
    const int n0 = blockIdx.x * 128;
    const int cb_w = warp_n * 64;

    // Load X tile 128x64 fp32 -> fp16 smem (once)
    #pragma unroll
    for (int it = 0; it < 8; it++) {
        const int f4 = tid + it * 256;         // 0..2047 float4s
        const int node = f4 >> 4;
        const int c4 = (f4 & 15) * 4;
        float4 v = *(const float4*)(X + (size_t)(n0 + node) * 64 + c4);
        *(__half2*)&As[node][c4]     = __floats2half2_rn(v.x, v.y);
        *(__half2*)&As[node][c4 + 2] = __floats2half2_rn(v.z, v.w);
    }

    // Prefill buffer 0 with z=0 weights
    {
        const __half* src = g_wt;
        #pragma unroll
        for (int it = 0; it < 4; it++) {
            const int idx = tid + it * 256;    // 0..1023
            const int nn = idx >> 3;
            const int k8 = (idx & 7) * 8;
            *(uint4*)&Bst[0][nn][k8] = *(const uint4*)(src + nn * 64 + k8);
        }
    }

    for (int z = 0; z < 12; z++) {
        const int h = z >> 2;
        const int kind = z & 3;
        const float* bias = nullptr;
        if (kind == 0)      bias = gate_b1 + h*128;
        else if (kind == 1) bias = msg_b1  + h*128;
        __half* table = (kind < 2) ? g_self_h : g_nbr_h;
        const bool is_msg = (kind & 1);
        const int buf = z & 1;

        __syncthreads();

        if (z < 11) {
            const __half* src = g_wt + (size_t)(z + 1) * 8192;
            #pragma unroll
            for (int it = 0; it < 4; it++) {
                const int idx = tid + it * 256;
                const int nn = idx >> 3;
                const int k8 = (idx & 7) * 8;
                *(uint4*)&Bst[buf ^ 1][nn][k8] = *(const uint4*)(src + nn * 64 + k8);
            }
        }

        float acc[2][8][4];
        #pragma unroll
        for (int m = 0; m < 2; m++)
            #pragma unroll
            for (int n = 0; n < 8; n++)
                #pragma unroll
                for (int j = 0; j < 4; j++) acc[m][n][j] = 0.f;

        #pragma unroll
        for (int ks = 0; ks < 4; ks++) {
            const int k0 = ks * 16;
            uint32_t a[2][4];
            #pragma unroll
            for (int m = 0; m < 2; m++) {
                const int rb = warp_m * 32 + m * 16;
                a[m][0] = *(const uint32_t*)&As[rb + gid    ][k0 + tig * 2];
                a[m][1] = *(const uint32_t*)&As[rb + gid + 8][k0 + tig * 2];
                a[m][2] = *(const uint32_t*)&As[rb + gid    ][k0 + 8 + tig * 2];
                a[m][3] = *(const uint32_t*)&As[rb + gid + 8][k0 + 8 + tig * 2];
            }
            uint32_t b[8][2];
            #pragma unroll
            for (int n = 0; n < 8; n++) {
                const int col = cb_w + n * 8 + gid;
                b[n][0] = *(const uint32_t*)&Bst[buf][col][k0 + tig * 2];
                b[n][1] = *(const uint32_t*)&Bst[buf][col][k0 + 8 + tig * 2];
            }
            #pragma unroll
            for (int m = 0; m < 2; m++)
                #pragma unroll
                for (int n = 0; n < 8; n++)
                    mma_f16(acc[m][n], a[m], b[n]);
        }

        // Epilogue: add bias, convert fp16, store interleaved node-major:
        // gate col c -> offset (c>>2)*8 + (c&3); msg col c -> (c>>2)*8 + 4 + (c&3)
        #pragma unroll
        for (int m = 0; m < 2; m++) {
            #pragma unroll
            for (int hr = 0; hr < 2; hr++) {
                const int row = n0 + warp_m * 32 + m * 16 + gid + hr * 8;
                __half* dst = table + ((size_t)row * 3 + h) * 256;
                #pragma unroll
                for (int n = 0; n < 8; n++) {
                    const int col = cb_w + n * 8 + 2 * tig;
                    float v0 = acc[m][n][hr * 2 + 0];
                    float v1 = acc[m][n][hr * 2 + 1];
                    if (bias) { v0 += bias[col]; v1 += bias[col + 1]; }
                    const int off = (col >> 2) * 8 + (col & 3) + (is_msg ? 4 : 0);
                    *(__half2*)(dst + off) = __floats2half2_rn(v0, v1);
                }
            }
        }
    }
}

// ---------------------------------------------------------------------------
// CSR row pointers from sorted self_fea_idx
// ---------------------------------------------------------------------------
__global__ void rowptr_kernel(const int* __restrict__ self_idx)
{
    const int e = blockIdx.x * blockDim.x + threadIdx.x;
    if (e >= M_EDGES) return;
    const int s = self_idx[e];
    const int prev = (e == 0) ? -1 : self_idx[e - 1];
    for (int n = prev + 1; n <= s; n++) g_rowptr[n] = e;
    if (e == M_EDGES - 1)
        for (int n = s + 1; n <= N_NODES; n++) g_rowptr[n] = M_EDGES;
}

// ---------------------------------------------------------------------------
// K2: fused softmax + weighted hidden accumulation.
// One warp per NODE, 3 heads fused; edge loop UNROLLED BY 2 with all 6 gathers
// (+2 idx +2 weight) issued before any use -> MLP=6 per warp. (R4's failure was
// a serialized 1-deep prefetch chain; this is batched-independent issue.)
// ---------------------------------------------------------------------------
__global__ void __launch_bounds__(128, 5)
edge_kernel(const int* __restrict__ nbr_idx,
            const float* __restrict__ elem_weights,
            const float* __restrict__ gate_w2,
            const float* __restrict__ gate_b2)
{
    const int n = blockIdx.x * 4 + (threadIdx.x >> 5);
    const int lane = threadIdx.x & 31;
    if (n >= N_NODES) return;

    // Self chunks + w2 + b2 per head
    float sg[3][4], sm[3][4], w2v[3][4], b2[3];
    #pragma unroll
    for (int h = 0; h < 3; h++) {
        const uint4 u = *(const uint4*)(g_self_h + ((size_t)n * 3 + h) * 256 + lane * 8);
        const float2 a0 = __half22float2(*(__half2*)&u.x);
        const float2 a1 = __half22float2(*(__half2*)&u.y);
        const float2 a2 = __half22float2(*(__half2*)&u.z);
        const float2 a3 = __half22float2(*(__half2*)&u.w);
        sg[h][0] = a0.x; sg[h][1] = a0.y; sg[h][2] = a1.x; sg[h][3] = a1.y;
        sm[h][0] = a2.x; sm[h][1] = a2.y; sm[h][2] = a3.x; sm[h][3] = a3.y;
        const float4 wv = *(const float4*)(gate_w2 + h * 128 + lane * 4);
        w2v[h][0] = wv.x; w2v[h][1] = wv.y; w2v[h][2] = wv.z; w2v[h][3] = wv.w;
        b2[h] = gate_b2[h];
    }

    const int e0 = g_rowptr[n];
    const int e1 = g_rowptr[n + 1];

    float acc[3][4];
    float denom[3] = {0.f, 0.f, 0.f};
    #pragma unroll
    for (int h = 0; h < 3; h++)
        #pragma unroll
        for (int d = 0; d < 4; d++) acc[h][d] = 0.f;

    int e = e0;
    for (; e + 1 < e1; e += 2) {
        // batched independent loads: 2 idx, 2 weights, 6 table gathers
        const int j0 = __ldg(&nbr_idx[e]);
        const int j1 = __ldg(&nbr_idx[e + 1]);
        const float w0 = __ldg(&elem_weights[j0]);
        const float w1 = __ldg(&elem_weights[j1]);
        uint4 u0[3], u1[3];
        #pragma unroll
        for (int h = 0; h < 3; h++) {
            u0[h] = *(const uint4*)(g_nbr_h + ((size_t)j0 * 3 + h) * 256 + lane * 8);
            u1[h] = *(const uint4*)(g_nbr_h + ((size_t)j1 * 3 + h) * 256 + lane * 8);
        }

        float p0[3], p1[3], m0[3][4], m1[3][4];
        #pragma unroll
        for (int h = 0; h < 3; h++) {
            {
                const float2 a0 = __half22float2(*(__half2*)&u0[h].x);
                const float2 a1 = __half22float2(*(__half2*)&u0[h].y);
                const float2 a2 = __half22float2(*(__half2*)&u0[h].z);
                const float2 a3 = __half22float2(*(__half2*)&u0[h].w);
                p0[h] = lk(sg[h][0] + a0.x) * w2v[h][0]
                      + lk(sg[h][1] + a0.y) * w2v[h][1]
                      + lk(sg[h][2] + a1.x) * w2v[h][2]
                      + lk(sg[h][3] + a1.y) * w2v[h][3];
                m0[h][0] = a2.x; m0[h][1] = a2.y; m0[h][2] = a3.x; m0[h][3] = a3.y;
            }
            {
                const float2 a0 = __half22float2(*(__half2*)&u1[h].x);
                const float2 a1 = __half22float2(*(__half2*)&u1[h].y);
                const float2 a2 = __half22float2(*(__half2*)&u1[h].z);
                const float2 a3 = __half22float2(*(__half2*)&u1[h].w);
                p1[h] = lk(sg[h][0] + a0.x) * w2v[h][0]
                      + lk(sg[h][1] + a0.y) * w2v[h][1]
                      + lk(sg[h][2] + a1.x) * w2v[h][2]
                      + lk(sg[h][3] + a1.y) * w2v[h][3];
                m1[h][0] = a2.x; m1[h][1] = a2.y; m1[h][2] = a3.x; m1[h][3] = a3.y;
            }
        }
        // 6 interleaved butterflies
        #pragma unroll
        for (int s = 16; s >= 1; s >>= 1) {
            p0[0] += __shfl_xor_sync(0xffffffffu, p0[0], s);
            p0[1] += __shfl_xor_sync(0xffffffffu, p0[1], s);
            p0[2] += __shfl_xor_sync(0xffffffffu, p0[2], s);
            p1[0] += __shfl_xor_sync(0xffffffffu, p1[0], s);
            p1[1] += __shfl_xor_sync(0xffffffffu, p1[1], s);
            p1[2] += __shfl_xor_sync(0xffffffffu, p1[2], s);
        }
        #pragma unroll
        for (int h = 0; h < 3; h++) {
            const float ev0 = w0 * __expf(p0[h] + b2[h]);
            const float ev1 = w1 * __expf(p1[h] + b2[h]);
            denom[h] += ev0 + ev1;
            acc[h][0] += ev0 * lk(sm[h][0] + m0[h][0]) + ev1 * lk(sm[h][0] + m1[h][0]);
            acc[h][1] += ev0 * lk(sm[h][1] + m0[h][1]) + ev1 * lk(sm[h][1] + m1[h][1]);
            acc[h][2] += ev0 * lk(sm[h][2] + m0[h][2]) + ev1 * lk(sm[h][2] + m1[h][2]);
            acc[h][3] += ev0 * lk(sm[h][3] + m0[h][3]) + ev1 * lk(sm[h][3] + m1[h][3]);
        }
    }
    // tail edge
    if (e < e1) {
        const int j = __ldg(&nbr_idx[e]);
        const float w = __ldg(&elem_weights[j]);
        uint4 u[3];
        #pragma unroll
        for (int h = 0; h < 3; h++)
            u[h] = *(const uint4*)(g_nbr_h + ((size_t)j * 3 + h) * 256 + lane * 8);
        float p[3], nm[3][4];
        #pragma unroll
        for (int h = 0; h < 3; h++) {
            const float2 a0 = __half22float2(*(__half2*)&u[h].x);
            const float2 a1 = __half22float2(*(__half2*)&u[h].y);
            const float2 a2 = __half22float2(*(__half2*)&u[h].z);
            const float2 a3 = __half22float2(*(__half2*)&u[h].w);
            p[h] = lk(sg[h][0] + a0.x) * w2v[h][0]
                 + lk(sg[h][1] + a0.y) * w2v[h][1]
                 + lk(sg[h][2] + a1.x) * w2v[h][2]
                 + lk(sg[h][3] + a1.y) * w2v[h][3];
            nm[h][0] = a2.x; nm[h][1] = a2.y; nm[h][2] = a3.x; nm[h][3] = a3.y;
        }
        #pragma unroll
        for (int s = 16; s >= 1; s >>= 1) {
            p[0] += __shfl_xor_sync(0xffffffffu, p[0], s);
            p[1] += __shfl_xor_sync(0xffffffffu, p[1], s);
            p[2] += __shfl_xor_sync(0xffffffffu, p[2], s);
        }
        #pragma unroll
        for (int h = 0; h < 3; h++) {
            const float ev = w * __expf(p[h] + b2[h]);
            denom[h] += ev;
            acc[h][0] += ev * lk(sm[h][0] + nm[h][0]);
            acc[h][1] += ev * lk(sm[h][1] + nm[h][1]);
            acc[h][2] += ev * lk(sm[h][2] + nm[h][2]);
            acc[h][3] += ev * lk(sm[h][3] + nm[h][3]);
        }
    }

    #pragma unroll
    for (int h = 0; h < 3; h++) {
        const float inv = 1.f / (denom[h] + 1e-10f);
        __half2 h0 = __floats2half2_rn(acc[h][0] * inv, acc[h][1] * inv);
        __half2 h1 = __floats2half2_rn(acc[h][2] * inv, acc[h][3] * inv);
        uint2 uo;
        uo.x = *(uint32_t*)&h0;
        uo.y = *(uint32_t*)&h1;
        *(uint2*)(g_acc_h + ((size_t)h * N_NODES + n) * 128 + lane * 4) = uo;
        if (lane == 0) g_sattn[(size_t)h * N_NODES + n] = denom[h] * inv;
    }
}

// ---------------------------------------------------------------------------
// K3: out[n][f] = x[n][f] + (1/3) * sum_h ( acc[h][n] @ msg_w2[h] + sattn[h][n]*msg_b2[h][f] )
// GEMM via fp16 mma.m16n8k16: C[N x 64] = A[N x 384] @ W[384 x 64]
// ---------------------------------------------------------------------------
__global__ void __launch_bounds__(256, 2)
out_gemm_kernel(const float* __restrict__ msg_w2,
                const float* __restrict__ msg_b2,
                const float* __restrict__ X,
                float* __restrict__ out)
{
    __shared__ __half As[128][88];   // 128 nodes x 64 k (fp16)
    __shared__ __half Bst[64][88];   // 64 cols x 64 k (transposed, fp16)

    const int tid  = threadIdx.x;    // 256 threads, 8 warps
    const int wid  = tid >> 5;
    const int lane = tid & 31;
    const int gid  = lane >> 2;      // 0..7
    const int tig  = lane & 3;       // 0..3
    const int warp_m = wid & 3;      // 4 warps over 128 rows (32 each)
    const int warp_n = wid >> 2;     // 2 warps over 64 cols (32 each)
    const int n0 = blockIdx.x * 128;
    const int cb = warp_n * 32;

    float acc[2][4][4];
    #pragma unroll
    for (int mt = 0; mt < 2; mt++)
        #pragma unroll
        for (int nt = 0; nt < 4; nt++)
            #pragma unroll
            for (int jj = 0; jj < 4; jj++) acc[mt][nt][jj] = 0.f;

    #pragma unroll
    for (int kc = 0; kc < 6; kc++) {
        const int h = kc >> 1;
        const __half* asrc = g_acc_h + ((size_t)h * N_NODES + n0) * 128 + (kc & 1) * 64;
        #pragma unroll
        for (int it = 0; it < 4; it++) {
            const int f4 = tid + it * 256;
            const int node = f4 >> 3;
            const int c8 = (f4 & 7) * 8;
            *(uint4*)&As[node][c8] = *(const uint4*)(asrc + (size_t)node * 128 + c8);
        }
        const float* bsrc = msg_w2 + ((size_t)h * 128 + (kc & 1) * 64) * 64;
        #pragma unroll
        for (int i = 0; i < 16; i++) {
            const int idx = i * 256 + tid;
            const int nn = idx & 63;
            const int kk = idx >> 6;
            Bst[nn][kk] = __float2half(bsrc[(size_t)kk * 64 + nn]);
        }
        __syncthreads();

        #pragma unroll
        for (int ks = 0; ks < 4; ks++) {
            const int k0 = ks * 16;
            uint32_t a[2][4];
            #pragma unroll
            for (int mt = 0; mt < 2; mt++) {
                const int rb = warp_m * 32 + mt * 16;
                a[mt][0] = *(const uint32_t*)&As[rb + gid    ][k0 + tig * 2];
                a[mt][1] = *(const uint32_t*)&As[rb + gid + 8][k0 + tig * 2];
                a[mt][2] = *(const uint32_t*)&As[rb + gid    ][k0 + 8 + tig * 2];
                a[mt][3] = *(const uint32_t*)&As[rb + gid + 8][k0 + 8 + tig * 2];
            }
            uint32_t b[4][2];
            #pragma unroll
            for (int nt = 0; nt < 4; nt++) {
                const int col = cb + nt * 8 + gid;
                b[nt][0] = *(const uint32_t*)&Bst[col][k0 + tig * 2];
                b[nt][1] = *(const uint32_t*)&Bst[col][k0 + 8 + tig * 2];
            }
            #pragma unroll
            for (int mt = 0; mt < 2; mt++)
                #pragma unroll
                for (int nt = 0; nt < 4; nt++)
                    mma_f16(acc[mt][nt], a[mt], b[nt]);
        }
        __syncthreads();
    }

    // Epilogue
    const float inv3 = 1.f / 3.f;
    #pragma unroll
    for (int mt = 0; mt < 2; mt++) {
        #pragma unroll
        for (int hf = 0; hf < 2; hf++) {
            const int r = n0 + warp_m * 32 + mt * 16 + gid + hf * 8;
            const float s0 = g_sattn[r];
            const float s1 = g_sattn[(size_t)N_NODES + r];
            const float s2 = g_sattn[(size_t)2 * N_NODES + r];
            #pragma unroll
            for (int nt = 0; nt < 4; nt++) {
                const int c = cb + nt * 8 + tig * 2;
                const float bt0 = s0 * msg_b2[c]     + s1 * msg_b2[64 + c]     + s2 * msg_b2[128 + c];
                const float bt1 = s0 * msg_b2[c + 1] + s1 * msg_b2[64 + c + 1] + s2 * msg_b2[128 + c + 1];
                const float2 xv = *(const float2*)(X + (size_t)r * 64 + c);
                float2 o;
                o.x = inv3 * (acc[mt][nt][hf * 2 + 0] + bt0) + xv.x;
                o.y = inv3 * (acc[mt][nt][hf * 2 + 1] + bt1) + xv.y;
                *(float2*)(out + (size_t)r * 64 + c) = o;
            }
        }
    }
}

// ---------------------------------------------------------------------------
extern "C" void kernel_launch(void* const* d_in, const int* in_sizes, int n_in,
                              void* d_out, int out_size)
{
    const float* elem_weights = (const float*)d_in[0];
    const float* x            = (const float*)d_in[1];
    const int*   self_idx     = (const int*)  d_in[2];
    const int*   nbr_idx      = (const int*)  d_in[3];
    const float* gate_w1      = (const float*)d_in[4];
    const float* gate_b1      = (const float*)d_in[5];
    const float* gate_w2      = (const float*)d_in[6];
    const float* gate_b2      = (const float*)d_in[7];
    const float* msg_w1       = (const float*)d_in[8];
    const float* msg_b1       = (const float*)d_in[9];
    const float* msg_w2       = (const float*)d_in[10];
    const float* msg_b2       = (const float*)d_in[11];
    float* out = (float*)d_out;

    prep_weights_kernel<<<12, 256>>>(gate_w1, msg_w1);
    node_gemm_kernel<<<N_NODES / 128, 256>>>(x, gate_b1, msg_b1);
    rowptr_kernel<<<M_EDGES / 256, 256>>>(self_idx);
    edge_kernel<<<N_NODES / 4, 128>>>(nbr_idx, elem_weights, gate_w2, gate_b2);
    out_gemm_kernel<<<N_NODES / 128, 256>>>(msg_w2, msg_b2, x, out);
}

// round 14
// speedup vs baseline: 1.0610x; 1.0610x over previous
#include <cuda_runtime.h>
#include <cuda_fp16.h>
#include <cstdint>

#define N_NODES 262144
#define M_EDGES 1048576
#define F_DIM   64
#define H_DIM   128
#define HEADS   3

// Scratch (static __device__ — no allocations allowed)
// Interleaved node-major fp16 tables: entry (n,h) = 256 halves; chunk l (8 halves
// at offset 8l): [gate[4l..4l+3], msg[4l..4l+3]]
__device__ __half g_self_h[(size_t)HEADS * N_NODES * 256];
__device__ __half g_nbr_h [(size_t)HEADS * N_NODES * 256];
__device__ __half g_acc_h[(size_t)HEADS * N_NODES * 128];  // fp16: sum_e attn*leaky(msg hidden)
__device__ float  g_sattn[(size_t)HEADS * N_NODES];        // sum_e attn
__device__ int    g_rowptr[N_NODES + 1];
// Pre-transposed fp16 W1 weights: [z][n][k], z = h*4 + kind
__device__ __half g_wt[12 * 128 * 64];

__device__ __forceinline__ float lk(float x) { return x >= 0.f ? x : 0.01f * x; }

__device__ __forceinline__ void mma_f16(float* c, const uint32_t* a, const uint32_t* b) {
    asm volatile(
        "mma.sync.aligned.m16n8k16.row.col.f32.f16.f16.f32 "
        "{%0,%1,%2,%3},{%4,%5,%6,%7},{%8,%9},{%0,%1,%2,%3};"
        : "+f"(c[0]), "+f"(c[1]), "+f"(c[2]), "+f"(c[3])
        : "r"(a[0]), "r"(a[1]), "r"(a[2]), "r"(a[3]), "r"(b[0]), "r"(b[1]));
}

__device__ __forceinline__ uint32_t smem_u32(const void* p) {
    return (uint32_t)__cvta_generic_to_shared(p);
}
__device__ __forceinline__ void cp16(uint32_t dst, const void* src) {
    asm volatile("cp.async.cg.shared.global [%0], [%1], 16;" :: "r"(dst), "l"(src));
}
__device__ __forceinline__ void cp4(uint32_t dst, const void* src) {
    asm volatile("cp.async.ca.shared.global [%0], [%1], 4;" :: "r"(dst), "l"(src));
}

// ---------------------------------------------------------------------------
// K0: convert+transpose all 12 W1 matrices to fp16 [n][k] layout, once.
// ---------------------------------------------------------------------------
__global__ void prep_weights_kernel(const float* __restrict__ gate_w1,
                                    const float* __restrict__ msg_w1)
{
    const int z = blockIdx.x;
    const int h = z >> 2;
    const int kind = z & 3;
    const float* W;
    if (kind == 0)      W = gate_w1 + (size_t)h*128*128;
    else if (kind == 1) W = msg_w1  + (size_t)h*128*128;
    else if (kind == 2) W = gate_w1 + (size_t)h*128*128 + 64*128;
    else                W = msg_w1  + (size_t)h*128*128 + 64*128;

    __half* dst = g_wt + (size_t)z * 8192;
    for (int i = threadIdx.x; i < 8192; i += 256) {
        const int n = i >> 6;
        const int k = i & 63;
        dst[i] = __float2half(W[(size_t)k * 128 + n]);
    }
}

// ---------------------------------------------------------------------------
// K1: fused node precompute. One block owns a 128-node X tile; loops over 12
// pre-transposed fp16 weight matrices, double-buffered, fp16 m16n8k16 MMA.
// Epilogue writes INTERLEAVED table layout (gate/msg chunks of 4).
// ---------------------------------------------------------------------------
__global__ void __launch_bounds__(256, 2)
node_gemm_kernel(const float* __restrict__ X,
                 const float* __restrict__ gate_b1,
                 const float* __restrict__ msg_b1)
{
    __shared__ __half As[128][72];       // 128 nodes x 64 k
    __shared__ __half Bst[2][128][72];   // double-buffered: 128 out-cols x 64 k

    const int tid  = threadIdx.x;     // 256 threads, 8 warps
    const int wid  = tid >> 5;
    const int lane = tid & 31;
    const int gid  = lane >> 2;       // 0..7
    const int tig  = lane & 3;        // 0..3
    const int warp_m = wid & 3;       // 4 warps over 128 rows
    const int warp_n = wid >> 2;      // 2 warps over 128 cols (64 each)
    const int n0 = blockIdx.x * 128;
    const int cb_w = warp_n * 64;

    // Load X tile 128x64 fp32 -> fp16 smem (once)
    #pragma unroll
    for (int it = 0; it < 8; it++) {
        const int f4 = tid + it * 256;         // 0..2047 float4s
        const int node = f4 >> 4;
        const int c4 = (f4 & 15) * 4;
        float4 v = *(const float4*)(X + (size_t)(n0 + node) * 64 + c4);
        *(__half2*)&As[node][c4]     = __floats2half2_rn(v.x, v.y);
        *(__half2*)&As[node][c4 + 2] = __floats2half2_rn(v.z, v.w);
    }

    // Prefill buffer 0 with z=0 weights
    {
        const __half* src = g_wt;
        #pragma unroll
        for (int it = 0; it < 4; it++) {
            const int idx = tid + it * 256;    // 0..1023
            const int nn = idx >> 3;
            const int k8 = (idx & 7) * 8;
            *(uint4*)&Bst[0][nn][k8] = *(const uint4*)(src + nn * 64 + k8);
        }
    }

    for (int z = 0; z < 12; z++) {
        const int h = z >> 2;
        const int kind = z & 3;
        const float* bias = nullptr;
        if (kind == 0)      bias = gate_b1 + h*128;
        else if (kind == 1) bias = msg_b1  + h*128;
        __half* table = (kind < 2) ? g_self_h : g_nbr_h;
        const bool is_msg = (kind & 1);
        const int buf = z & 1;

        __syncthreads();

        if (z < 11) {
            const __half* src = g_wt + (size_t)(z + 1) * 8192;
            #pragma unroll
            for (int it = 0; it < 4; it++) {
                const int idx = tid + it * 256;
                const int nn = idx >> 3;
                const int k8 = (idx & 7) * 8;
                *(uint4*)&Bst[buf ^ 1][nn][k8] = *(const uint4*)(src + nn * 64 + k8);
            }
        }

        float acc[2][8][4];
        #pragma unroll
        for (int m = 0; m < 2; m++)
            #pragma unroll
            for (int n = 0; n < 8; n++)
                #pragma unroll
                for (int j = 0; j < 4; j++) acc[m][n][j] = 0.f;

        #pragma unroll
        for (int ks = 0; ks < 4; ks++) {
            const int k0 = ks * 16;
            uint32_t a[2][4];
            #pragma unroll
            for (int m = 0; m < 2; m++) {
                const int rb = warp_m * 32 + m * 16;
                a[m][0] = *(const uint32_t*)&As[rb + gid    ][k0 + tig * 2];
                a[m][1] = *(const uint32_t*)&As[rb + gid + 8][k0 + tig * 2];
                a[m][2] = *(const uint32_t*)&As[rb + gid    ][k0 + 8 + tig * 2];
                a[m][3] = *(const uint32_t*)&As[rb + gid + 8][k0 + 8 + tig * 2];
            }
            uint32_t b[8][2];
            #pragma unroll
            for (int n = 0; n < 8; n++) {
                const int col = cb_w + n * 8 + gid;
                b[n][0] = *(const uint32_t*)&Bst[buf][col][k0 + tig * 2];
                b[n][1] = *(const uint32_t*)&Bst[buf][col][k0 + 8 + tig * 2];
            }
            #pragma unroll
            for (int m = 0; m < 2; m++)
                #pragma unroll
                for (int n = 0; n < 8; n++)
                    mma_f16(acc[m][n], a[m], b[n]);
        }

        // Epilogue: add bias, convert fp16, store interleaved node-major:
        // gate col c -> offset (c>>2)*8 + (c&3); msg col c -> (c>>2)*8 + 4 + (c&3)
        #pragma unroll
        for (int m = 0; m < 2; m++) {
            #pragma unroll
            for (int hr = 0; hr < 2; hr++) {
                const int row = n0 + warp_m * 32 + m * 16 + gid + hr * 8;
                __half* dst = table + ((size_t)row * 3 + h) * 256;
                #pragma unroll
                for (int n = 0; n < 8; n++) {
                    const int col = cb_w + n * 8 + 2 * tig;
                    float v0 = acc[m][n][hr * 2 + 0];
                    float v1 = acc[m][n][hr * 2 + 1];
                    if (bias) { v0 += bias[col]; v1 += bias[col + 1]; }
                    const int off = (col >> 2) * 8 + (col & 3) + (is_msg ? 4 : 0);
                    *(__half2*)(dst + off) = __floats2half2_rn(v0, v1);
                }
            }
        }
    }
}

// ---------------------------------------------------------------------------
// CSR row pointers from sorted self_fea_idx
// ---------------------------------------------------------------------------
__global__ void rowptr_kernel(const int* __restrict__ self_idx)
{
    const int e = blockIdx.x * blockDim.x + threadIdx.x;
    if (e >= M_EDGES) return;
    const int s = self_idx[e];
    const int prev = (e == 0) ? -1 : self_idx[e - 1];
    for (int n = prev + 1; n <= s; n++) g_rowptr[n] = e;
    if (e == M_EDGES - 1)
        for (int n = s + 1; n <= N_NODES; n++) g_rowptr[n] = M_EDGES;
}

// ---------------------------------------------------------------------------
// K2: fused softmax + weighted hidden accumulation.
// One warp per NODE, 3 heads fused. Gathers go global->shared via cp.async
// (LDGSTS): DEPTH-deep per-warp smem ring decouples MLP from the register
// file (R13 post-mortem: registers were the MLP bottleneck). One commit_group
// per edge (empty groups keep counts aligned); wait_group(DEPTH-1) => edge i's
// group complete at iteration i. Edge weight rides in the slot header (cp4 by
// lane 0, published by __syncwarp after the wait). nbr index for edge i+DEPTH
// prefetched one iteration ahead in a register (no dependent-load stall).
// ---------------------------------------------------------------------------
#define EDEPTH 3
#define SLOT_BYTES 1552   // 16B header (w at +0) + 3 heads x 512B

__global__ void __launch_bounds__(128, 6)
edge_kernel(const int* __restrict__ nbr_idx,
            const float* __restrict__ elem_weights,
            const float* __restrict__ gate_w2,
            const float* __restrict__ gate_b2)
{
    __shared__ __align__(16) unsigned char buf[4][EDEPTH][SLOT_BYTES];

    const int wslot = threadIdx.x >> 5;
    const int lane  = threadIdx.x & 31;
    const int n = blockIdx.x * 4 + wslot;
    if (n >= N_NODES) return;

    // Self chunks + w2 + b2 per head
    float sg[3][4], sm[3][4], w2v[3][4], b2[3];
    #pragma unroll
    for (int h = 0; h < 3; h++) {
        const uint4 u = *(const uint4*)(g_self_h + ((size_t)n * 3 + h) * 256 + lane * 8);
        const float2 a0 = __half22float2(*(__half2*)&u.x);
        const float2 a1 = __half22float2(*(__half2*)&u.y);
        const float2 a2 = __half22float2(*(__half2*)&u.z);
        const float2 a3 = __half22float2(*(__half2*)&u.w);
        sg[h][0] = a0.x; sg[h][1] = a0.y; sg[h][2] = a1.x; sg[h][3] = a1.y;
        sm[h][0] = a2.x; sm[h][1] = a2.y; sm[h][2] = a3.x; sm[h][3] = a3.y;
        const float4 wv = *(const float4*)(gate_w2 + h * 128 + lane * 4);
        w2v[h][0] = wv.x; w2v[h][1] = wv.y; w2v[h][2] = wv.z; w2v[h][3] = wv.w;
        b2[h] = gate_b2[h];
    }

    const int e0 = g_rowptr[n];
    const int e1 = g_rowptr[n + 1];
    const int deg = e1 - e0;

    const uint32_t sbase = smem_u32(&buf[wslot][0][0]);

    // Prologue: prefetch first EDEPTH edges (independent idx loads).
    #pragma unroll
    for (int d = 0; d < EDEPTH; d++) {
        if (d < deg) {
            const int j = __ldg(&nbr_idx[e0 + d]);
            const uint32_t sb = sbase + d * SLOT_BYTES;
            const __half* src = g_nbr_h + (size_t)j * 768 + lane * 8;
            const uint32_t dd = sb + 16 + lane * 16;
            cp16(dd,        src);
            cp16(dd + 512,  src + 256);
            cp16(dd + 1024, src + 512);
            if (lane == 0) cp4(sb, elem_weights + j);
        }
        asm volatile("cp.async.commit_group;" ::: "memory");
    }
    int jn = 0;
    if (EDEPTH < deg) jn = __ldg(&nbr_idx[e0 + EDEPTH]);

    float acc[3][4];
    float denom[3] = {0.f, 0.f, 0.f};
    #pragma unroll
    for (int h = 0; h < 3; h++)
        #pragma unroll
        for (int d = 0; d < 4; d++) acc[h][d] = 0.f;

    int slot = 0;
    for (int i = 0; i < deg; i++) {
        asm volatile("cp.async.wait_group %0;" :: "n"(EDEPTH - 1) : "memory");
        __syncwarp();

        const unsigned char* sp = &buf[wslot][slot][0];
        const float w = *(const float*)sp;
        uint4 u[3];
        #pragma unroll
        for (int h = 0; h < 3; h++)
            u[h] = *(const uint4*)(sp + 16 + h * 512 + lane * 16);

        // Prefetch edge i+EDEPTH into this slot (data already read into regs)
        const int ipf = i + EDEPTH;
        if (ipf < deg) {
            const uint32_t sb = sbase + slot * SLOT_BYTES;
            const __half* src = g_nbr_h + (size_t)jn * 768 + lane * 8;
            const uint32_t dd = sb + 16 + lane * 16;
            cp16(dd,        src);
            cp16(dd + 512,  src + 256);
            cp16(dd + 1024, src + 512);
            if (lane == 0) cp4(sb, elem_weights + jn);
            if (ipf + 1 < deg) jn = __ldg(&nbr_idx[e0 + ipf + 1]);
        }
        asm volatile("cp.async.commit_group;" ::: "memory");

        float p[3], nm[3][4];
        #pragma unroll
        for (int h = 0; h < 3; h++) {
            const float2 a0 = __half22float2(*(__half2*)&u[h].x);
            const float2 a1 = __half22float2(*(__half2*)&u[h].y);
            const float2 a2 = __half22float2(*(__half2*)&u[h].z);
            const float2 a3 = __half22float2(*(__half2*)&u[h].w);
            p[h] = lk(sg[h][0] + a0.x) * w2v[h][0]
                 + lk(sg[h][1] + a0.y) * w2v[h][1]
                 + lk(sg[h][2] + a1.x) * w2v[h][2]
                 + lk(sg[h][3] + a1.y) * w2v[h][3];
            nm[h][0] = a2.x; nm[h][1] = a2.y; nm[h][2] = a3.x; nm[h][3] = a3.y;
        }
        #pragma unroll
        for (int s = 16; s >= 1; s >>= 1) {
            p[0] += __shfl_xor_sync(0xffffffffu, p[0], s);
            p[1] += __shfl_xor_sync(0xffffffffu, p[1], s);
            p[2] += __shfl_xor_sync(0xffffffffu, p[2], s);
        }
        #pragma unroll
        for (int h = 0; h < 3; h++) {
            const float ev = w * __expf(p[h] + b2[h]);
            denom[h] += ev;
            acc[h][0] += ev * lk(sm[h][0] + nm[h][0]);
            acc[h][1] += ev * lk(sm[h][1] + nm[h][1]);
            acc[h][2] += ev * lk(sm[h][2] + nm[h][2]);
            acc[h][3] += ev * lk(sm[h][3] + nm[h][3]);
        }

        slot = (slot + 1 == EDEPTH) ? 0 : slot + 1;
    }

    #pragma unroll
    for (int h = 0; h < 3; h++) {
        const float inv = 1.f / (denom[h] + 1e-10f);
        __half2 h0 = __floats2half2_rn(acc[h][0] * inv, acc[h][1] * inv);
        __half2 h1 = __floats2half2_rn(acc[h][2] * inv, acc[h][3] * inv);
        uint2 uo;
        uo.x = *(uint32_t*)&h0;
        uo.y = *(uint32_t*)&h1;
        *(uint2*)(g_acc_h + ((size_t)h * N_NODES + n) * 128 + lane * 4) = uo;
        if (lane == 0) g_sattn[(size_t)h * N_NODES + n] = denom[h] * inv;
    }
}

// ---------------------------------------------------------------------------
// K3: out[n][f] = x[n][f] + (1/3) * sum_h ( acc[h][n] @ msg_w2[h] + sattn[h][n]*msg_b2[h][f] )
// GEMM via fp16 mma.m16n8k16: C[N x 64] = A[N x 384] @ W[384 x 64]
// ---------------------------------------------------------------------------
__global__ void __launch_bounds__(256, 2)
out_gemm_kernel(const float* __restrict__ msg_w2,
                const float* __restrict__ msg_b2,
                const float* __restrict__ X,
                float* __restrict__ out)
{
    __shared__ __half As[128][88];   // 128 nodes x 64 k (fp16)
    __shared__ __half Bst[64][88];   // 64 cols x 64 k (transposed, fp16)

    const int tid  = threadIdx.x;    // 256 threads, 8 warps
    const int wid  = tid >> 5;
    const int lane = tid & 31;
    const int gid  = lane >> 2;      // 0..7
    const int tig  = lane & 3;       // 0..3
    const int warp_m = wid & 3;      // 4 warps over 128 rows (32 each)
    const int warp_n = wid >> 2;     // 2 warps over 64 cols (32 each)
    const int n0 = blockIdx.x * 128;
    const int cb = warp_n * 32;

    float acc[2][4][4];
    #pragma unroll
    for (int mt = 0; mt < 2; mt++)
        #pragma unroll
        for (int nt = 0; nt < 4; nt++)
            #pragma unroll
            for (int jj = 0; jj < 4; jj++) acc[mt][nt][jj] = 0.f;

    #pragma unroll
    for (int kc = 0; kc < 6; kc++) {
        const int h = kc >> 1;
        const __half* asrc = g_acc_h + ((size_t)h * N_NODES + n0) * 128 + (kc & 1) * 64;
        #pragma unroll
        for (int it = 0; it < 4; it++) {
            const int f4 = tid + it * 256;
            const int node = f4 >> 3;
            const int c8 = (f4 & 7) * 8;
            *(uint4*)&As[node][c8] = *(const uint4*)(asrc + (size_t)node * 128 + c8);
        }
        const float* bsrc = msg_w2 + ((size_t)h * 128 + (kc & 1) * 64) * 64;
        #pragma unroll
        for (int i = 0; i < 16; i++) {
            const int idx = i * 256 + tid;
            const int nn = idx & 63;
            const int kk = idx >> 6;
            Bst[nn][kk] = __float2half(bsrc[(size_t)kk * 64 + nn]);
        }
        __syncthreads();

        #pragma unroll
        for (int ks = 0; ks < 4; ks++) {
            const int k0 = ks * 16;
            uint32_t a[2][4];
            #pragma unroll
            for (int mt = 0; mt < 2; mt++) {
                const int rb = warp_m * 32 + mt * 16;
                a[mt][0] = *(const uint32_t*)&As[rb + gid    ][k0 + tig * 2];
                a[mt][1] = *(const uint32_t*)&As[rb + gid + 8][k0 + tig * 2];
                a[mt][2] = *(const uint32_t*)&As[rb + gid    ][k0 + 8 + tig * 2];
                a[mt][3] = *(const uint32_t*)&As[rb + gid + 8][k0 + 8 + tig * 2];
            }
            uint32_t b[4][2];
            #pragma unroll
            for (int nt = 0; nt < 4; nt++) {
                const int col = cb + nt * 8 + gid;
                b[nt][0] = *(const uint32_t*)&Bst[col][k0 + tig * 2];
                b[nt][1] = *(const uint32_t*)&Bst[col][k0 + 8 + tig * 2];
            }
            #pragma unroll
            for (int mt = 0; mt < 2; mt++)
                #pragma unroll
                for (int nt = 0; nt < 4; nt++)
                    mma_f16(acc[mt][nt], a[mt], b[nt]);
        }
        __syncthreads();
    }

    // Epilogue
    const float inv3 = 1.f / 3.f;
    #pragma unroll
    for (int mt = 0; mt < 2; mt++) {
        #pragma unroll
        for (int hf = 0; hf < 2; hf++) {
            const int r = n0 + warp_m * 32 + mt * 16 + gid + hf * 8;
            const float s0 = g_sattn[r];
            const float s1 = g_sattn[(size_t)N_NODES + r];
            const float s2 = g_sattn[(size_t)2 * N_NODES + r];
            #pragma unroll
            for (int nt = 0; nt < 4; nt++) {
                const int c = cb + nt * 8 + tig * 2;
                const float bt0 = s0 * msg_b2[c]     + s1 * msg_b2[64 + c]     + s2 * msg_b2[128 + c];
                const float bt1 = s0 * msg_b2[c + 1] + s1 * msg_b2[64 + c + 1] + s2 * msg_b2[128 + c + 1];
                const float2 xv = *(const float2*)(X + (size_t)r * 64 + c);
                float2 o;
                o.x = inv3 * (acc[mt][nt][hf * 2 + 0] + bt0) + xv.x;
                o.y = inv3 * (acc[mt][nt][hf * 2 + 1] + bt1) + xv.y;
                *(float2*)(out + (size_t)r * 64 + c) = o;
            }
        }
    }
}

// ---------------------------------------------------------------------------
extern "C" void kernel_launch(void* const* d_in, const int* in_sizes, int n_in,
                              void* d_out, int out_size)
{
    const float* elem_weights = (const float*)d_in[0];
    const float* x            = (const float*)d_in[1];
    const int*   self_idx     = (const int*)  d_in[2];
    const int*   nbr_idx      = (const int*)  d_in[3];
    const float* gate_w1      = (const float*)d_in[4];
    const float* gate_b1      = (const float*)d_in[5];
    const float* gate_w2      = (const float*)d_in[6];
    const float* gate_b2      = (const float*)d_in[7];
    const float* msg_w1       = (const float*)d_in[8];
    const float* msg_b1       = (const float*)d_in[9];
    const float* msg_w2       = (const float*)d_in[10];
    const float* msg_b2       = (const float*)d_in[11];
    float* out = (float*)d_out;

    prep_weights_kernel<<<12, 256>>>(gate_w1, msg_w1);
    node_gemm_kernel<<<N_NODES / 128, 256>>>(x, gate_b1, msg_b1);
    rowptr_kernel<<<M_EDGES / 256, 256>>>(self_idx);
    edge_kernel<<<N_NODES / 4, 128>>>(nbr_idx, elem_weights, gate_w2, gate_b2);
    out_gemm_kernel<<<N_NODES / 128, 256>>>(msg_w2, msg_b2, x, out);
}

// round 15
// speedup vs baseline: 1.1751x; 1.1076x over previous
#include <cuda_runtime.h>
#include <cuda_fp16.h>
#include <cstdint>

#define N_NODES 262144
#define M_EDGES 1048576
#define F_DIM   64
#define H_DIM   128
#define HEADS   3

// Scratch (static __device__ — no allocations allowed)
// Interleaved node-major fp16 tables: entry (n,h) = 256 halves; chunk l (8 halves
// at offset 8l): [gate[4l..4l+3], msg[4l..4l+3]]
__device__ __half g_self_h[(size_t)HEADS * N_NODES * 256];
__device__ __half g_nbr_h [(size_t)HEADS * N_NODES * 256];
__device__ __half g_acc_h[(size_t)HEADS * N_NODES * 128];  // fp16: sum_e attn*leaky(msg hidden)
__device__ float  g_sattn[(size_t)HEADS * N_NODES];        // sum_e attn
__device__ int    g_rowptr[N_NODES + 1];
// Pre-transposed fp16 W1 weights: [z][n][k], z = h*4 + kind
__device__ __half g_wt[12 * 128 * 64];

__device__ __forceinline__ float lk(float x) { return x >= 0.f ? x : 0.01f * x; }

__device__ __forceinline__ void mma_f16(float* c, const uint32_t* a, const uint32_t* b) {
    asm volatile(
        "mma.sync.aligned.m16n8k16.row.col.f32.f16.f16.f32 "
        "{%0,%1,%2,%3},{%4,%5,%6,%7},{%8,%9},{%0,%1,%2,%3};"
        : "+f"(c[0]), "+f"(c[1]), "+f"(c[2]), "+f"(c[3])
        : "r"(a[0]), "r"(a[1]), "r"(a[2]), "r"(a[3]), "r"(b[0]), "r"(b[1]));
}

__device__ __forceinline__ uint32_t smem_u32(const void* p) {
    return (uint32_t)__cvta_generic_to_shared(p);
}
__device__ __forceinline__ void cp16(uint32_t dst, const void* src) {
    asm volatile("cp.async.cg.shared.global [%0], [%1], 16;" :: "r"(dst), "l"(src));
}
__device__ __forceinline__ void cp4(uint32_t dst, const void* src) {
    asm volatile("cp.async.ca.shared.global [%0], [%1], 4;" :: "r"(dst), "l"(src));
}

// ---------------------------------------------------------------------------
// K0: convert+transpose all 12 W1 matrices to fp16 [n][k] layout, once.
// ---------------------------------------------------------------------------
__global__ void prep_weights_kernel(const float* __restrict__ gate_w1,
                                    const float* __restrict__ msg_w1)
{
    const int z = blockIdx.x;
    const int h = z >> 2;
    const int kind = z & 3;
    const float* W;
    if (kind == 0)      W = gate_w1 + (size_t)h*128*128;
    else if (kind == 1) W = msg_w1  + (size_t)h*128*128;
    else if (kind == 2) W = gate_w1 + (size_t)h*128*128 + 64*128;
    else                W = msg_w1  + (size_t)h*128*128 + 64*128;

    __half* dst = g_wt + (size_t)z * 8192;
    for (int i = threadIdx.x; i < 8192; i += 256) {
        const int n = i >> 6;
        const int k = i & 63;
        dst[i] = __float2half(W[(size_t)k * 128 + n]);
    }
}

// ---------------------------------------------------------------------------
// K1: fused node precompute, pair-fused epilogue.
// One block owns a 128-node X tile. Loops over 6 (head, table) PAIRS; each
// pair runs the gate GEMM then the msg GEMM, staging both into a smem tile
// (interleaved offsets), then copies out full 512B rows with uint4 stores
// (R14 post-mortem: scattered 4B epilogue stores caused ~2x write
// amplification — node_gemm was write-bound, not MMA-bound).
// Dynamic smem: As 18432 + Bst 18432 + stage 67584 = 104448 B.
// ---------------------------------------------------------------------------
#define NG_SMEM (18432 + 18432 + 67584)

__global__ void __launch_bounds__(256, 2)
node_gemm_kernel(const float* __restrict__ X,
                 const float* __restrict__ gate_b1,
                 const float* __restrict__ msg_b1)
{
    extern __shared__ __align__(16) unsigned char dynsmem[];
    __half (*As)[72]     = (__half(*)[72])(dynsmem);            // 128 x 72
    __half (*Bst)[72]    = (__half(*)[72])(dynsmem + 18432);    // 128 x 72
    __half (*stage)[264] = (__half(*)[264])(dynsmem + 36864);   // 128 x 264

    const int tid  = threadIdx.x;     // 256 threads, 8 warps
    const int wid  = tid >> 5;
    const int lane = tid & 31;
    const int gid  = lane >> 2;       // 0..7
    const int tig  = lane & 3;        // 0..3
    const int warp_m = wid & 3;       // 4 warps over 128 rows
    const int warp_n = wid >> 2;      // 2 warps over 128 cols (64 each)
    const int n0 = blockIdx.x * 128;
    const int cb_w = warp_n * 64;

    // Load X tile 128x64 fp32 -> fp16 smem (once)
    #pragma unroll
    for (int it = 0; it < 8; it++) {
        const int f4 = tid + it * 256;         // 0..2047 float4s
        const int node = f4 >> 4;
        const int c4 = (f4 & 15) * 4;
        float4 v = *(const float4*)(X + (size_t)(n0 + node) * 64 + c4);
        *(__half2*)&As[node][c4]     = __floats2half2_rn(v.x, v.y);
        *(__half2*)&As[node][c4 + 2] = __floats2half2_rn(v.z, v.w);
    }

    for (int pair = 0; pair < 6; pair++) {
        const int h = pair >> 1;
        const int t = pair & 1;                 // 0 = self, 1 = nbr
        __half* table = t ? g_nbr_h : g_self_h;

        #pragma unroll
        for (int sub = 0; sub < 2; sub++) {     // 0 = gate, 1 = msg
            const int z = h * 4 + t * 2 + sub;
            const float* bias = nullptr;
            if (t == 0) bias = (sub == 0) ? gate_b1 + h * 128 : msg_b1 + h * 128;

            __syncthreads();   // prev MMA reads of Bst done; prev copyout of stage done
            // Fill Bst (vectorized: 1024 uint4s)
            {
                const __half* src = g_wt + (size_t)z * 8192;
                #pragma unroll
                for (int it = 0; it < 4; it++) {
                    const int idx = tid + it * 256;    // 0..1023
                    const int nn = idx >> 3;
                    const int k8 = (idx & 7) * 8;
                    *(uint4*)&Bst[nn][k8] = *(const uint4*)(src + nn * 64 + k8);
                }
            }
            __syncthreads();

            float acc[2][8][4];
            #pragma unroll
            for (int m = 0; m < 2; m++)
                #pragma unroll
                for (int n = 0; n < 8; n++)
                    #pragma unroll
                    for (int j = 0; j < 4; j++) acc[m][n][j] = 0.f;

            #pragma unroll
            for (int ks = 0; ks < 4; ks++) {
                const int k0 = ks * 16;
                uint32_t a[2][4];
                #pragma unroll
                for (int m = 0; m < 2; m++) {
                    const int rb = warp_m * 32 + m * 16;
                    a[m][0] = *(const uint32_t*)&As[rb + gid    ][k0 + tig * 2];
                    a[m][1] = *(const uint32_t*)&As[rb + gid + 8][k0 + tig * 2];
                    a[m][2] = *(const uint32_t*)&As[rb + gid    ][k0 + 8 + tig * 2];
                    a[m][3] = *(const uint32_t*)&As[rb + gid + 8][k0 + 8 + tig * 2];
                }
                uint32_t b[8][2];
                #pragma unroll
                for (int n = 0; n < 8; n++) {
                    const int col = cb_w + n * 8 + gid;
                    b[n][0] = *(const uint32_t*)&Bst[col][k0 + tig * 2];
                    b[n][1] = *(const uint32_t*)&Bst[col][k0 + 8 + tig * 2];
                }
                #pragma unroll
                for (int m = 0; m < 2; m++)
                    #pragma unroll
                    for (int n = 0; n < 8; n++)
                        mma_f16(acc[m][n], a[m], b[n]);
            }

            // Stage acc (+bias) at interleaved offsets:
            // col c, sub s -> (c>>2)*8 + (c&3) + 4s
            #pragma unroll
            for (int m = 0; m < 2; m++) {
                #pragma unroll
                for (int hr = 0; hr < 2; hr++) {
                    const int row = warp_m * 32 + m * 16 + gid + hr * 8;
                    #pragma unroll
                    for (int n = 0; n < 8; n++) {
                        const int col = cb_w + n * 8 + 2 * tig;
                        float v0 = acc[m][n][hr * 2 + 0];
                        float v1 = acc[m][n][hr * 2 + 1];
                        if (bias) { v0 += bias[col]; v1 += bias[col + 1]; }
                        const int off = (col >> 2) * 8 + (col & 3) + sub * 4;
                        *(__half2*)&stage[row][off] = __floats2half2_rn(v0, v1);
                    }
                }
            }
        }

        __syncthreads();   // stage complete (both subs)
        // Copy out: each warp writes full 512B rows (8x uint4 per row)
        #pragma unroll
        for (int it = 0; it < 16; it++) {
            const int idx = tid + it * 256;    // 0..4095
            const int r  = idx >> 5;
            const int c8 = (idx & 31) * 8;
            __half* gdst = table + ((size_t)(n0 + r) * 3 + h) * 256 + c8;
            *(uint4*)gdst = *(const uint4*)&stage[r][c8];
        }
    }
}

// ---------------------------------------------------------------------------
// CSR row pointers from sorted self_fea_idx
// ---------------------------------------------------------------------------
__global__ void rowptr_kernel(const int* __restrict__ self_idx)
{
    const int e = blockIdx.x * blockDim.x + threadIdx.x;
    if (e >= M_EDGES) return;
    const int s = self_idx[e];
    const int prev = (e == 0) ? -1 : self_idx[e - 1];
    for (int n = prev + 1; n <= s; n++) g_rowptr[n] = e;
    if (e == M_EDGES - 1)
        for (int n = s + 1; n <= N_NODES; n++) g_rowptr[n] = M_EDGES;
}

// ---------------------------------------------------------------------------
// K2: fused softmax + weighted hidden accumulation.
// One warp per NODE, 3 heads fused, cp.async smem ring (EDEPTH deep).
// ---------------------------------------------------------------------------
#define EDEPTH 4
#define SLOT_BYTES 1552   // 16B header (w at +0) + 3 heads x 512B

__global__ void __launch_bounds__(128, 6)
edge_kernel(const int* __restrict__ nbr_idx,
            const float* __restrict__ elem_weights,
            const float* __restrict__ gate_w2,
            const float* __restrict__ gate_b2)
{
    __shared__ __align__(16) unsigned char buf[4][EDEPTH][SLOT_BYTES];

    const int wslot = threadIdx.x >> 5;
    const int lane  = threadIdx.x & 31;
    const int n = blockIdx.x * 4 + wslot;
    if (n >= N_NODES) return;

    // Self chunks + w2 + b2 per head
    float sg[3][4], sm[3][4], w2v[3][4], b2[3];
    #pragma unroll
    for (int h = 0; h < 3; h++) {
        const uint4 u = *(const uint4*)(g_self_h + ((size_t)n * 3 + h) * 256 + lane * 8);
        const float2 a0 = __half22float2(*(__half2*)&u.x);
        const float2 a1 = __half22float2(*(__half2*)&u.y);
        const float2 a2 = __half22float2(*(__half2*)&u.z);
        const float2 a3 = __half22float2(*(__half2*)&u.w);
        sg[h][0] = a0.x; sg[h][1] = a0.y; sg[h][2] = a1.x; sg[h][3] = a1.y;
        sm[h][0] = a2.x; sm[h][1] = a2.y; sm[h][2] = a3.x; sm[h][3] = a3.y;
        const float4 wv = *(const float4*)(gate_w2 + h * 128 + lane * 4);
        w2v[h][0] = wv.x; w2v[h][1] = wv.y; w2v[h][2] = wv.z; w2v[h][3] = wv.w;
        b2[h] = gate_b2[h];
    }

    const int e0 = g_rowptr[n];
    const int e1 = g_rowptr[n + 1];
    const int deg = e1 - e0;

    const uint32_t sbase = smem_u32(&buf[wslot][0][0]);

    // Prologue: prefetch first EDEPTH edges (independent idx loads).
    #pragma unroll
    for (int d = 0; d < EDEPTH; d++) {
        if (d < deg) {
            const int j = __ldg(&nbr_idx[e0 + d]);
            const uint32_t sb = sbase + d * SLOT_BYTES;
            const __half* src = g_nbr_h + (size_t)j * 768 + lane * 8;
            const uint32_t dd = sb + 16 + lane * 16;
            cp16(dd,        src);
            cp16(dd + 512,  src + 256);
            cp16(dd + 1024, src + 512);
            if (lane == 0) cp4(sb, elem_weights + j);
        }
        asm volatile("cp.async.commit_group;" ::: "memory");
    }
    int jn = 0;
    if (EDEPTH < deg) jn = __ldg(&nbr_idx[e0 + EDEPTH]);

    float acc[3][4];
    float denom[3] = {0.f, 0.f, 0.f};
    #pragma unroll
    for (int h = 0; h < 3; h++)
        #pragma unroll
        for (int d = 0; d < 4; d++) acc[h][d] = 0.f;

    int slot = 0;
    for (int i = 0; i < deg; i++) {
        asm volatile("cp.async.wait_group %0;" :: "n"(EDEPTH - 1) : "memory");
        __syncwarp();

        const unsigned char* sp = &buf[wslot][slot][0];
        const float w = *(const float*)sp;
        uint4 u[3];
        #pragma unroll
        for (int h = 0; h < 3; h++)
            u[h] = *(const uint4*)(sp + 16 + h * 512 + lane * 16);

        // Prefetch edge i+EDEPTH into this slot (data already read into regs)
        const int ipf = i + EDEPTH;
        if (ipf < deg) {
            const uint32_t sb = sbase + slot * SLOT_BYTES;
            const __half* src = g_nbr_h + (size_t)jn * 768 + lane * 8;
            const uint32_t dd = sb + 16 + lane * 16;
            cp16(dd,        src);
            cp16(dd + 512,  src + 256);
            cp16(dd + 1024, src + 512);
            if (lane == 0) cp4(sb, elem_weights + jn);
            if (ipf + 1 < deg) jn = __ldg(&nbr_idx[e0 + ipf + 1]);
        }
        asm volatile("cp.async.commit_group;" ::: "memory");

        float p[3], nm[3][4];
        #pragma unroll
        for (int h = 0; h < 3; h++) {
            const float2 a0 = __half22float2(*(__half2*)&u[h].x);
            const float2 a1 = __half22float2(*(__half2*)&u[h].y);
            const float2 a2 = __half22float2(*(__half2*)&u[h].z);
            const float2 a3 = __half22float2(*(__half2*)&u[h].w);
            p[h] = lk(sg[h][0] + a0.x) * w2v[h][0]
                 + lk(sg[h][1] + a0.y) * w2v[h][1]
                 + lk(sg[h][2] + a1.x) * w2v[h][2]
                 + lk(sg[h][3] + a1.y) * w2v[h][3];
            nm[h][0] = a2.x; nm[h][1] = a2.y; nm[h][2] = a3.x; nm[h][3] = a3.y;
        }
        #pragma unroll
        for (int s = 16; s >= 1; s >>= 1) {
            p[0] += __shfl_xor_sync(0xffffffffu, p[0], s);
            p[1] += __shfl_xor_sync(0xffffffffu, p[1], s);
            p[2] += __shfl_xor_sync(0xffffffffu, p[2], s);
        }
        #pragma unroll
        for (int h = 0; h < 3; h++) {
            const float ev = w * __expf(p[h] + b2[h]);
            denom[h] += ev;
            acc[h][0] += ev * lk(sm[h][0] + nm[h][0]);
            acc[h][1] += ev * lk(sm[h][1] + nm[h][1]);
            acc[h][2] += ev * lk(sm[h][2] + nm[h][2]);
            acc[h][3] += ev * lk(sm[h][3] + nm[h][3]);
        }

        slot = (slot + 1 == EDEPTH) ? 0 : slot + 1;
    }

    #pragma unroll
    for (int h = 0; h < 3; h++) {
        const float inv = 1.f / (denom[h] + 1e-10f);
        __half2 h0 = __floats2half2_rn(acc[h][0] * inv, acc[h][1] * inv);
        __half2 h1 = __floats2half2_rn(acc[h][2] * inv, acc[h][3] * inv);
        uint2 uo;
        uo.x = *(uint32_t*)&h0;
        uo.y = *(uint32_t*)&h1;
        *(uint2*)(g_acc_h + ((size_t)h * N_NODES + n) * 128 + lane * 4) = uo;
        if (lane == 0) g_sattn[(size_t)h * N_NODES + n] = denom[h] * inv;
    }
}

// ---------------------------------------------------------------------------
// K3: out[n][f] = x[n][f] + (1/3) * sum_h ( acc[h][n] @ msg_w2[h] + sattn[h][n]*msg_b2[h][f] )
// GEMM via fp16 mma.m16n8k16: C[N x 64] = A[N x 384] @ W[384 x 64]
// ---------------------------------------------------------------------------
__global__ void __launch_bounds__(256, 2)
out_gemm_kernel(const float* __restrict__ msg_w2,
                const float* __restrict__ msg_b2,
                const float* __restrict__ X,
                float* __restrict__ out)
{
    __shared__ __half As[128][88];   // 128 nodes x 64 k (fp16)
    __shared__ __half Bst[64][88];   // 64 cols x 64 k (transposed, fp16)

    const int tid  = threadIdx.x;    // 256 threads, 8 warps
    const int wid  = tid >> 5;
    const int lane = tid & 31;
    const int gid  = lane >> 2;      // 0..7
    const int tig  = lane & 3;       // 0..3
    const int warp_m = wid & 3;      // 4 warps over 128 rows (32 each)
    const int warp_n = wid >> 2;     // 2 warps over 64 cols (32 each)
    const int n0 = blockIdx.x * 128;
    const int cb = warp_n * 32;

    float acc[2][4][4];
    #pragma unroll
    for (int mt = 0; mt < 2; mt++)
        #pragma unroll
        for (int nt = 0; nt < 4; nt++)
            #pragma unroll
            for (int jj = 0; jj < 4; jj++) acc[mt][nt][jj] = 0.f;

    #pragma unroll
    for (int kc = 0; kc < 6; kc++) {
        const int h = kc >> 1;
        const __half* asrc = g_acc_h + ((size_t)h * N_NODES + n0) * 128 + (kc & 1) * 64;
        #pragma unroll
        for (int it = 0; it < 4; it++) {
            const int f4 = tid + it * 256;
            const int node = f4 >> 3;
            const int c8 = (f4 & 7) * 8;
            *(uint4*)&As[node][c8] = *(const uint4*)(asrc + (size_t)node * 128 + c8);
        }
        const float* bsrc = msg_w2 + ((size_t)h * 128 + (kc & 1) * 64) * 64;
        #pragma unroll
        for (int i = 0; i < 16; i++) {
            const int idx = i * 256 + tid;
            const int nn = idx & 63;
            const int kk = idx >> 6;
            Bst[nn][kk] = __float2half(bsrc[(size_t)kk * 64 + nn]);
        }
        __syncthreads();

        #pragma unroll
        for (int ks = 0; ks < 4; ks++) {
            const int k0 = ks * 16;
            uint32_t a[2][4];
            #pragma unroll
            for (int mt = 0; mt < 2; mt++) {
                const int rb = warp_m * 32 + mt * 16;
                a[mt][0] = *(const uint32_t*)&As[rb + gid    ][k0 + tig * 2];
                a[mt][1] = *(const uint32_t*)&As[rb + gid + 8][k0 + tig * 2];
                a[mt][2] = *(const uint32_t*)&As[rb + gid    ][k0 + 8 + tig * 2];
                a[mt][3] = *(const uint32_t*)&As[rb + gid + 8][k0 + 8 + tig * 2];
            }
            uint32_t b[4][2];
            #pragma unroll
            for (int nt = 0; nt < 4; nt++) {
                const int col = cb + nt * 8 + gid;
                b[nt][0] = *(const uint32_t*)&Bst[col][k0 + tig * 2];
                b[nt][1] = *(const uint32_t*)&Bst[col][k0 + 8 + tig * 2];
            }
            #pragma unroll
            for (int mt = 0; mt < 2; mt++)
                #pragma unroll
                for (int nt = 0; nt < 4; nt++)
                    mma_f16(acc[mt][nt], a[mt], b[nt]);
        }
        __syncthreads();
    }

    // Epilogue
    const float inv3 = 1.f / 3.f;
    #pragma unroll
    for (int mt = 0; mt < 2; mt++) {
        #pragma unroll
        for (int hf = 0; hf < 2; hf++) {
            const int r = n0 + warp_m * 32 + mt * 16 + gid + hf * 8;
            const float s0 = g_sattn[r];
            const float s1 = g_sattn[(size_t)N_NODES + r];
            const float s2 = g_sattn[(size_t)2 * N_NODES + r];
            #pragma unroll
            for (int nt = 0; nt < 4; nt++) {
                const int c = cb + nt * 8 + tig * 2;
                const float bt0 = s0 * msg_b2[c]     + s1 * msg_b2[64 + c]     + s2 * msg_b2[128 + c];
                const float bt1 = s0 * msg_b2[c + 1] + s1 * msg_b2[64 + c + 1] + s2 * msg_b2[128 + c + 1];
                const float2 xv = *(const float2*)(X + (size_t)r * 64 + c);
                float2 o;
                o.x = inv3 * (acc[mt][nt][hf * 2 + 0] + bt0) + xv.x;
                o.y = inv3 * (acc[mt][nt][hf * 2 + 1] + bt1) + xv.y;
                *(float2*)(out + (size_t)r * 64 + c) = o;
            }
        }
    }
}

// ---------------------------------------------------------------------------
extern "C" void kernel_launch(void* const* d_in, const int* in_sizes, int n_in,
                              void* d_out, int out_size)
{
    const float* elem_weights = (const float*)d_in[0];
    const float* x            = (const float*)d_in[1];
    const int*   self_idx     = (const int*)  d_in[2];
    const int*   nbr_idx      = (const int*)  d_in[3];
    const float* gate_w1      = (const float*)d_in[4];
    const float* gate_b1      = (const float*)d_in[5];
    const float* gate_w2      = (const float*)d_in[6];
    const float* gate_b2      = (const float*)d_in[7];
    const float* msg_w1       = (const float*)d_in[8];
    const float* msg_b1       = (const float*)d_in[9];
    const float* msg_w2       = (const float*)d_in[10];
    const float* msg_b2       = (const float*)d_in[11];
    float* out = (float*)d_out;

    static bool attr_set = false;
    if (!attr_set) {
        cudaFuncSetAttribute(node_gemm_kernel,
                             cudaFuncAttributeMaxDynamicSharedMemorySize, NG_SMEM);
        attr_set = true;
    }

    prep_weights_kernel<<<12, 256>>>(gate_w1, msg_w1);
    node_gemm_kernel<<<N_NODES / 128, 256, NG_SMEM>>>(x, gate_b1, msg_b1);
    rowptr_kernel<<<M_EDGES / 256, 256>>>(self_idx);
    edge_kernel<<<N_NODES / 4, 128>>>(nbr_idx, elem_weights, gate_w2, gate_b2);
    out_gemm_kernel<<<N_NODES / 128, 256>>>(msg_w2, msg_b2, x, out);
}

// round 16
// speedup vs baseline: 1.3700x; 1.1658x over previous
#include <cuda_runtime.h>
#include <cuda_fp16.h>
#include <cstdint>

#define N_NODES 262144
#define M_EDGES 1048576
#define F_DIM   64
#define H_DIM   128
#define HEADS   3

// Scratch (static __device__ — no allocations allowed)
// Interleaved node-major fp16 tables: entry (n,h) = 256 halves; chunk l (8 halves
// at offset 8l): [gate[4l..4l+3], msg[4l..4l+3]]
__device__ __half g_self_h[(size_t)HEADS * N_NODES * 256];
__device__ __half g_nbr_h [(size_t)HEADS * N_NODES * 256];
__device__ __half g_acc_h[(size_t)HEADS * N_NODES * 128];  // fp16: sum_e attn*leaky(msg hidden)
__device__ float  g_sattn[(size_t)HEADS * N_NODES];        // sum_e attn
__device__ int    g_rowptr[N_NODES + 1];
// Pre-transposed fp16 W1 weights: [z][n][k], z = h*4 + kind
__device__ __half g_wt[12 * 128 * 64];
// Work-stealing counter for edge_kernel (reset by rowptr_kernel each launch)
__device__ unsigned int g_work;

__device__ __forceinline__ float lk(float x) { return x >= 0.f ? x : 0.01f * x; }

__device__ __forceinline__ void mma_f16(float* c, const uint32_t* a, const uint32_t* b) {
    asm volatile(
        "mma.sync.aligned.m16n8k16.row.col.f32.f16.f16.f32 "
        "{%0,%1,%2,%3},{%4,%5,%6,%7},{%8,%9},{%0,%1,%2,%3};"
        : "+f"(c[0]), "+f"(c[1]), "+f"(c[2]), "+f"(c[3])
        : "r"(a[0]), "r"(a[1]), "r"(a[2]), "r"(a[3]), "r"(b[0]), "r"(b[1]));
}

__device__ __forceinline__ uint32_t smem_u32(const void* p) {
    return (uint32_t)__cvta_generic_to_shared(p);
}
__device__ __forceinline__ void cp16(uint32_t dst, const void* src) {
    asm volatile("cp.async.cg.shared.global [%0], [%1], 16;" :: "r"(dst), "l"(src));
}
__device__ __forceinline__ void cp4(uint32_t dst, const void* src) {
    asm volatile("cp.async.ca.shared.global [%0], [%1], 4;" :: "r"(dst), "l"(src));
}

// ---------------------------------------------------------------------------
// K0: convert+transpose all 12 W1 matrices to fp16 [n][k] layout, once.
// ---------------------------------------------------------------------------
__global__ void prep_weights_kernel(const float* __restrict__ gate_w1,
                                    const float* __restrict__ msg_w1)
{
    const int z = blockIdx.x;
    const int h = z >> 2;
    const int kind = z & 3;
    const float* W;
    if (kind == 0)      W = gate_w1 + (size_t)h*128*128;
    else if (kind == 1) W = msg_w1  + (size_t)h*128*128;
    else if (kind == 2) W = gate_w1 + (size_t)h*128*128 + 64*128;
    else                W = msg_w1  + (size_t)h*128*128 + 64*128;

    __half* dst = g_wt + (size_t)z * 8192;
    for (int i = threadIdx.x; i < 8192; i += 256) {
        const int n = i >> 6;
        const int k = i & 63;
        dst[i] = __float2half(W[(size_t)k * 128 + n]);
    }
}

// ---------------------------------------------------------------------------
// K1: fused node precompute, pair-fused epilogue (full-row uint4 copyout).
// Dynamic smem: As 18432 + Bst 18432 + stage 67584 = 104448 B.
// ---------------------------------------------------------------------------
#define NG_SMEM (18432 + 18432 + 67584)

__global__ void __launch_bounds__(256, 2)
node_gemm_kernel(const float* __restrict__ X,
                 const float* __restrict__ gate_b1,
                 const float* __restrict__ msg_b1)
{
    extern __shared__ __align__(16) unsigned char dynsmem[];
    __half (*As)[72]     = (__half(*)[72])(dynsmem);            // 128 x 72
    __half (*Bst)[72]    = (__half(*)[72])(dynsmem + 18432);    // 128 x 72
    __half (*stage)[264] = (__half(*)[264])(dynsmem + 36864);   // 128 x 264

    const int tid  = threadIdx.x;     // 256 threads, 8 warps
    const int wid  = tid >> 5;
    const int lane = tid & 31;
    const int gid  = lane >> 2;       // 0..7
    const int tig  = lane & 3;        // 0..3
    const int warp_m = wid & 3;       // 4 warps over 128 rows
    const int warp_n = wid >> 2;      // 2 warps over 128 cols (64 each)
    const int n0 = blockIdx.x * 128;
    const int cb_w = warp_n * 64;

    // Load X tile 128x64 fp32 -> fp16 smem (once)
    #pragma unroll
    for (int it = 0; it < 8; it++) {
        const int f4 = tid + it * 256;         // 0..2047 float4s
        const int node = f4 >> 4;
        const int c4 = (f4 & 15) * 4;
        float4 v = *(const float4*)(X + (size_t)(n0 + node) * 64 + c4);
        *(__half2*)&As[node][c4]     = __floats2half2_rn(v.x, v.y);
        *(__half2*)&As[node][c4 + 2] = __floats2half2_rn(v.z, v.w);
    }

    for (int pair = 0; pair < 6; pair++) {
        const int h = pair >> 1;
        const int t = pair & 1;                 // 0 = self, 1 = nbr
        __half* table = t ? g_nbr_h : g_self_h;

        #pragma unroll
        for (int sub = 0; sub < 2; sub++) {     // 0 = gate, 1 = msg
            const int z = h * 4 + t * 2 + sub;
            const float* bias = nullptr;
            if (t == 0) bias = (sub == 0) ? gate_b1 + h * 128 : msg_b1 + h * 128;

            __syncthreads();   // prev MMA reads of Bst done; prev copyout of stage done
            // Fill Bst (vectorized: 1024 uint4s)
            {
                const __half* src = g_wt + (size_t)z * 8192;
                #pragma unroll
                for (int it = 0; it < 4; it++) {
                    const int idx = tid + it * 256;    // 0..1023
                    const int nn = idx >> 3;
                    const int k8 = (idx & 7) * 8;
                    *(uint4*)&Bst[nn][k8] = *(const uint4*)(src + nn * 64 + k8);
                }
            }
            __syncthreads();

            float acc[2][8][4];
            #pragma unroll
            for (int m = 0; m < 2; m++)
                #pragma unroll
                for (int n = 0; n < 8; n++)
                    #pragma unroll
                    for (int j = 0; j < 4; j++) acc[m][n][j] = 0.f;

            #pragma unroll
            for (int ks = 0; ks < 4; ks++) {
                const int k0 = ks * 16;
                uint32_t a[2][4];
                #pragma unroll
                for (int m = 0; m < 2; m++) {
                    const int rb = warp_m * 32 + m * 16;
                    a[m][0] = *(const uint32_t*)&As[rb + gid    ][k0 + tig * 2];
                    a[m][1] = *(const uint32_t*)&As[rb + gid + 8][k0 + tig * 2];
                    a[m][2] = *(const uint32_t*)&As[rb + gid    ][k0 + 8 + tig * 2];
                    a[m][3] = *(const uint32_t*)&As[rb + gid + 8][k0 + 8 + tig * 2];
                }
                uint32_t b[8][2];
                #pragma unroll
                for (int n = 0; n < 8; n++) {
                    const int col = cb_w + n * 8 + gid;
                    b[n][0] = *(const uint32_t*)&Bst[col][k0 + tig * 2];
                    b[n][1] = *(const uint32_t*)&Bst[col][k0 + 8 + tig * 2];
                }
                #pragma unroll
                for (int m = 0; m < 2; m++)
                    #pragma unroll
                    for (int n = 0; n < 8; n++)
                        mma_f16(acc[m][n], a[m], b[n]);
            }

            // Stage acc (+bias) at interleaved offsets:
            // col c, sub s -> (c>>2)*8 + (c&3) + 4s
            #pragma unroll
            for (int m = 0; m < 2; m++) {
                #pragma unroll
                for (int hr = 0; hr < 2; hr++) {
                    const int row = warp_m * 32 + m * 16 + gid + hr * 8;
                    #pragma unroll
                    for (int n = 0; n < 8; n++) {
                        const int col = cb_w + n * 8 + 2 * tig;
                        float v0 = acc[m][n][hr * 2 + 0];
                        float v1 = acc[m][n][hr * 2 + 1];
                        if (bias) { v0 += bias[col]; v1 += bias[col + 1]; }
                        const int off = (col >> 2) * 8 + (col & 3) + sub * 4;
                        *(__half2*)&stage[row][off] = __floats2half2_rn(v0, v1);
                    }
                }
            }
        }

        __syncthreads();   // stage complete (both subs)
        // Copy out: full 512B rows (8x uint4 per row)
        #pragma unroll
        for (int it = 0; it < 16; it++) {
            const int idx = tid + it * 256;    // 0..4095
            const int r  = idx >> 5;
            const int c8 = (idx & 31) * 8;
            __half* gdst = table + ((size_t)(n0 + r) * 3 + h) * 256 + c8;
            *(uint4*)gdst = *(const uint4*)&stage[r][c8];
        }
    }
}

// ---------------------------------------------------------------------------
// CSR row pointers from sorted self_fea_idx; also resets the work counter.
// ---------------------------------------------------------------------------
__global__ void rowptr_kernel(const int* __restrict__ self_idx)
{
    const int e = blockIdx.x * blockDim.x + threadIdx.x;
    if (e >= M_EDGES) return;
    if (e == 0) g_work = 0u;
    const int s = self_idx[e];
    const int prev = (e == 0) ? -1 : self_idx[e - 1];
    for (int n = prev + 1; n <= s; n++) g_rowptr[n] = e;
    if (e == M_EDGES - 1)
        for (int n = s + 1; n <= N_NODES; n++) g_rowptr[n] = M_EDGES;
}

// ---------------------------------------------------------------------------
// K2: fused softmax + weighted hidden accumulation.
// Persistent warps + batched work-stealing: each warp atomically grabs 4
// consecutive nodes at a time (R15 post-mortem: degree imbalance held CTA
// slots hostage — achieved occ 27% vs 37.5%). 3 heads fused, cp.async smem
// ring (EDEPTH=3; 4 measured worse). Node-invariant w2/b2 hoisted out of the
// node loop. Group accounting across node boundaries is safe: pending groups
// at a node's end are all empty commits (prefetches beyond deg predicated off).
// ---------------------------------------------------------------------------
#define EDEPTH 3
#define SLOT_BYTES 1552   // 16B header (w at +0) + 3 heads x 512B
#define EGRID 1024

__global__ void __launch_bounds__(128, 6)
edge_kernel(const int* __restrict__ nbr_idx,
            const float* __restrict__ elem_weights,
            const float* __restrict__ gate_w2,
            const float* __restrict__ gate_b2)
{
    __shared__ __align__(16) unsigned char buf[4][EDEPTH][SLOT_BYTES];

    const int wslot = threadIdx.x >> 5;
    const int lane  = threadIdx.x & 31;

    // Node-invariant per-head gate vectors
    float w2v[3][4], b2[3];
    #pragma unroll
    for (int h = 0; h < 3; h++) {
        const float4 wv = *(const float4*)(gate_w2 + h * 128 + lane * 4);
        w2v[h][0] = wv.x; w2v[h][1] = wv.y; w2v[h][2] = wv.z; w2v[h][3] = wv.w;
        b2[h] = gate_b2[h];
    }

    const uint32_t sbase = smem_u32(&buf[wslot][0][0]);

    for (;;) {
        int base;
        if (lane == 0) base = (int)atomicAdd(&g_work, 4u);
        base = __shfl_sync(0xffffffffu, base, 0);
        if (base >= N_NODES) return;
        const int nend = (base + 4 < N_NODES) ? base + 4 : N_NODES;

        for (int n = base; n < nend; n++) {
            // Self chunks per head
            float sg[3][4], sm[3][4];
            #pragma unroll
            for (int h = 0; h < 3; h++) {
                const uint4 u = *(const uint4*)(g_self_h + ((size_t)n * 3 + h) * 256 + lane * 8);
                const float2 a0 = __half22float2(*(__half2*)&u.x);
                const float2 a1 = __half22float2(*(__half2*)&u.y);
                const float2 a2 = __half22float2(*(__half2*)&u.z);
                const float2 a3 = __half22float2(*(__half2*)&u.w);
                sg[h][0] = a0.x; sg[h][1] = a0.y; sg[h][2] = a1.x; sg[h][3] = a1.y;
                sm[h][0] = a2.x; sm[h][1] = a2.y; sm[h][2] = a3.x; sm[h][3] = a3.y;
            }

            const int e0 = g_rowptr[n];
            const int e1 = g_rowptr[n + 1];
            const int deg = e1 - e0;

            // Prologue: prefetch first EDEPTH edges
            #pragma unroll
            for (int d = 0; d < EDEPTH; d++) {
                if (d < deg) {
                    const int j = __ldg(&nbr_idx[e0 + d]);
                    const uint32_t sb = sbase + d * SLOT_BYTES;
                    const __half* src = g_nbr_h + (size_t)j * 768 + lane * 8;
                    const uint32_t dd = sb + 16 + lane * 16;
                    cp16(dd,        src);
                    cp16(dd + 512,  src + 256);
                    cp16(dd + 1024, src + 512);
                    if (lane == 0) cp4(sb, elem_weights + j);
                }
                asm volatile("cp.async.commit_group;" ::: "memory");
            }
            int jn = 0;
            if (EDEPTH < deg) jn = __ldg(&nbr_idx[e0 + EDEPTH]);

            float acc[3][4];
            float denom[3] = {0.f, 0.f, 0.f};
            #pragma unroll
            for (int h = 0; h < 3; h++)
                #pragma unroll
                for (int d = 0; d < 4; d++) acc[h][d] = 0.f;

            int slot = 0;
            for (int i = 0; i < deg; i++) {
                asm volatile("cp.async.wait_group %0;" :: "n"(EDEPTH - 1) : "memory");
                __syncwarp();

                const unsigned char* sp = &buf[wslot][slot][0];
                const float w = *(const float*)sp;
                uint4 u[3];
                #pragma unroll
                for (int h = 0; h < 3; h++)
                    u[h] = *(const uint4*)(sp + 16 + h * 512 + lane * 16);

                const int ipf = i + EDEPTH;
                if (ipf < deg) {
                    const uint32_t sb = sbase + slot * SLOT_BYTES;
                    const __half* src = g_nbr_h + (size_t)jn * 768 + lane * 8;
                    const uint32_t dd = sb + 16 + lane * 16;
                    cp16(dd,        src);
                    cp16(dd + 512,  src + 256);
                    cp16(dd + 1024, src + 512);
                    if (lane == 0) cp4(sb, elem_weights + jn);
                    if (ipf + 1 < deg) jn = __ldg(&nbr_idx[e0 + ipf + 1]);
                }
                asm volatile("cp.async.commit_group;" ::: "memory");

                float p[3], nm[3][4];
                #pragma unroll
                for (int h = 0; h < 3; h++) {
                    const float2 a0 = __half22float2(*(__half2*)&u[h].x);
                    const float2 a1 = __half22float2(*(__half2*)&u[h].y);
                    const float2 a2 = __half22float2(*(__half2*)&u[h].z);
                    const float2 a3 = __half22float2(*(__half2*)&u[h].w);
                    p[h] = lk(sg[h][0] + a0.x) * w2v[h][0]
                         + lk(sg[h][1] + a0.y) * w2v[h][1]
                         + lk(sg[h][2] + a1.x) * w2v[h][2]
                         + lk(sg[h][3] + a1.y) * w2v[h][3];
                    nm[h][0] = a2.x; nm[h][1] = a2.y; nm[h][2] = a3.x; nm[h][3] = a3.y;
                }
                #pragma unroll
                for (int s = 16; s >= 1; s >>= 1) {
                    p[0] += __shfl_xor_sync(0xffffffffu, p[0], s);
                    p[1] += __shfl_xor_sync(0xffffffffu, p[1], s);
                    p[2] += __shfl_xor_sync(0xffffffffu, p[2], s);
                }
                #pragma unroll
                for (int h = 0; h < 3; h++) {
                    const float ev = w * __expf(p[h] + b2[h]);
                    denom[h] += ev;
                    acc[h][0] += ev * lk(sm[h][0] + nm[h][0]);
                    acc[h][1] += ev * lk(sm[h][1] + nm[h][1]);
                    acc[h][2] += ev * lk(sm[h][2] + nm[h][2]);
                    acc[h][3] += ev * lk(sm[h][3] + nm[h][3]);
                }

                slot = (slot + 1 == EDEPTH) ? 0 : slot + 1;
            }

            #pragma unroll
            for (int h = 0; h < 3; h++) {
                const float inv = 1.f / (denom[h] + 1e-10f);
                __half2 h0 = __floats2half2_rn(acc[h][0] * inv, acc[h][1] * inv);
                __half2 h1 = __floats2half2_rn(acc[h][2] * inv, acc[h][3] * inv);
                uint2 uo;
                uo.x = *(uint32_t*)&h0;
                uo.y = *(uint32_t*)&h1;
                *(uint2*)(g_acc_h + ((size_t)h * N_NODES + n) * 128 + lane * 4) = uo;
                if (lane == 0) g_sattn[(size_t)h * N_NODES + n] = denom[h] * inv;
            }
        }
    }
}

// ---------------------------------------------------------------------------
// K3: out[n][f] = x[n][f] + (1/3) * sum_h ( acc[h][n] @ msg_w2[h] + sattn[h][n]*msg_b2[h][f] )
// GEMM via fp16 mma.m16n8k16: C[N x 64] = A[N x 384] @ W[384 x 64]
// ---------------------------------------------------------------------------
__global__ void __launch_bounds__(256, 2)
out_gemm_kernel(const float* __restrict__ msg_w2,
                const float* __restrict__ msg_b2,
                const float* __restrict__ X,
                float* __restrict__ out)
{
    __shared__ __half As[128][88];   // 128 nodes x 64 k (fp16)
    __shared__ __half Bst[64][88];   // 64 cols x 64 k (transposed, fp16)

    const int tid  = threadIdx.x;    // 256 threads, 8 warps
    const int wid  = tid >> 5;
    const int lane = tid & 31;
    const int gid  = lane >> 2;      // 0..7
    const int tig  = lane & 3;       // 0..3
    const int warp_m = wid & 3;      // 4 warps over 128 rows (32 each)
    const int warp_n = wid >> 2;     // 2 warps over 64 cols (32 each)
    const int n0 = blockIdx.x * 128;
    const int cb = warp_n * 32;

    float acc[2][4][4];
    #pragma unroll
    for (int mt = 0; mt < 2; mt++)
        #pragma unroll
        for (int nt = 0; nt < 4; nt++)
            #pragma unroll
            for (int jj = 0; jj < 4; jj++) acc[mt][nt][jj] = 0.f;

    #pragma unroll
    for (int kc = 0; kc < 6; kc++) {
        const int h = kc >> 1;
        const __half* asrc = g_acc_h + ((size_t)h * N_NODES + n0) * 128 + (kc & 1) * 64;
        #pragma unroll
        for (int it = 0; it < 4; it++) {
            const int f4 = tid + it * 256;
            const int node = f4 >> 3;
            const int c8 = (f4 & 7) * 8;
            *(uint4*)&As[node][c8] = *(const uint4*)(asrc + (size_t)node * 128 + c8);
        }
        const float* bsrc = msg_w2 + ((size_t)h * 128 + (kc & 1) * 64) * 64;
        #pragma unroll
        for (int i = 0; i < 16; i++) {
            const int idx = i * 256 + tid;
            const int nn = idx & 63;
            const int kk = idx >> 6;
            Bst[nn][kk] = __float2half(bsrc[(size_t)kk * 64 + nn]);
        }
        __syncthreads();

        #pragma unroll
        for (int ks = 0; ks < 4; ks++) {
            const int k0 = ks * 16;
            uint32_t a[2][4];
            #pragma unroll
            for (int mt = 0; mt < 2; mt++) {
                const int rb = warp_m * 32 + mt * 16;
                a[mt][0] = *(const uint32_t*)&As[rb + gid    ][k0 + tig * 2];
                a[mt][1] = *(const uint32_t*)&As[rb + gid + 8][k0 + tig * 2];
                a[mt][2] = *(const uint32_t*)&As[rb + gid    ][k0 + 8 + tig * 2];
                a[mt][3] = *(const uint32_t*)&As[rb + gid + 8][k0 + 8 + tig * 2];
            }
            uint32_t b[4][2];
            #pragma unroll
            for (int nt = 0; nt < 4; nt++) {
                const int col = cb + nt * 8 + gid;
                b[nt][0] = *(const uint32_t*)&Bst[col][k0 + tig * 2];
                b[nt][1] = *(const uint32_t*)&Bst[col][k0 + 8 + tig * 2];
            }
            #pragma unroll
            for (int mt = 0; mt < 2; mt++)
                #pragma unroll
                for (int nt = 0; nt < 4; nt++)
                    mma_f16(acc[mt][nt], a[mt], b[nt]);
        }
        __syncthreads();
    }

    // Epilogue
    const float inv3 = 1.f / 3.f;
    #pragma unroll
    for (int mt = 0; mt < 2; mt++) {
        #pragma unroll
        for (int hf = 0; hf < 2; hf++) {
            const int r = n0 + warp_m * 32 + mt * 16 + gid + hf * 8;
            const float s0 = g_sattn[r];
            const float s1 = g_sattn[(size_t)N_NODES + r];
            const float s2 = g_sattn[(size_t)2 * N_NODES + r];
            #pragma unroll
            for (int nt = 0; nt < 4; nt++) {
                const int c = cb + nt * 8 + tig * 2;
                const float bt0 = s0 * msg_b2[c]     + s1 * msg_b2[64 + c]     + s2 * msg_b2[128 + c];
                const float bt1 = s0 * msg_b2[c + 1] + s1 * msg_b2[64 + c + 1] + s2 * msg_b2[128 + c + 1];
                const float2 xv = *(const float2*)(X + (size_t)r * 64 + c);
                float2 o;
                o.x = inv3 * (acc[mt][nt][hf * 2 + 0] + bt0) + xv.x;
                o.y = inv3 * (acc[mt][nt][hf * 2 + 1] + bt1) + xv.y;
                *(float2*)(out + (size_t)r * 64 + c) = o;
            }
        }
    }
}

// ---------------------------------------------------------------------------
extern "C" void kernel_launch(void* const* d_in, const int* in_sizes, int n_in,
                              void* d_out, int out_size)
{
    const float* elem_weights = (const float*)d_in[0];
    const float* x            = (const float*)d_in[1];
    const int*   self_idx     = (const int*)  d_in[2];
    const int*   nbr_idx      = (const int*)  d_in[3];
    const float* gate_w1      = (const float*)d_in[4];
    const float* gate_b1      = (const float*)d_in[5];
    const float* gate_w2      = (const float*)d_in[6];
    const float* gate_b2      = (const float*)d_in[7];
    const float* msg_w1       = (const float*)d_in[8];
    const float* msg_b1       = (const float*)d_in[9];
    const float* msg_w2       = (const float*)d_in[10];
    const float* msg_b2       = (const float*)d_in[11];
    float* out = (float*)d_out;

    static bool attr_set = false;
    if (!attr_set) {
        cudaFuncSetAttribute(node_gemm_kernel,
                             cudaFuncAttributeMaxDynamicSharedMemorySize, NG_SMEM);
        attr_set = true;
    }

    prep_weights_kernel<<<12, 256>>>(gate_w1, msg_w1);
    node_gemm_kernel<<<N_NODES / 128, 256, NG_SMEM>>>(x, gate_b1, msg_b1);
    rowptr_kernel<<<M_EDGES / 256, 256>>>(self_idx);
    edge_kernel<<<EGRID, 128>>>(nbr_idx, elem_weights, gate_w2, gate_b2);
    out_gemm_kernel<<<N_NODES / 128, 256>>>(msg_w2, msg_b2, x, out);
}

// round 17
// speedup vs baseline: 1.3957x; 1.0188x over previous
#include <cuda_runtime.h>
#include <cuda_fp16.h>
#include <cstdint>

#define N_NODES 262144
#define M_EDGES 1048576
#define F_DIM   64
#define H_DIM   128
#define HEADS   3

// Scratch (static __device__ — no allocations allowed)
// Interleaved node-major fp16 tables: entry (n,h) = 256 halves; chunk l (8 halves
// at offset 8l): [gate[4l..4l+3], msg[4l..4l+3]]
__device__ __half g_self_h[(size_t)HEADS * N_NODES * 256];
__device__ __half g_nbr_h [(size_t)HEADS * N_NODES * 256];
__device__ __half g_acc_h[(size_t)HEADS * N_NODES * 128];  // fp16: sum_e attn*leaky(msg hidden)
__device__ float  g_sattn[(size_t)HEADS * N_NODES];        // sum_e attn
__device__ int    g_rowptr[N_NODES + 1];
// Pre-transposed fp16 W1 weights: [z][n][k], z = h*4 + kind
__device__ __half g_wt[12 * 128 * 64];
// Pre-transposed fp16 msg_w2: [h][n][k] (n = out col 0..63, k = 0..127)
__device__ __half g_wt2[3 * 64 * 128];
// Work-stealing counter for edge_kernel (reset by rowptr_kernel each launch)
__device__ unsigned int g_work;

__device__ __forceinline__ float lk(float x) { return x >= 0.f ? x : 0.01f * x; }

__device__ __forceinline__ void mma_f16(float* c, const uint32_t* a, const uint32_t* b) {
    asm volatile(
        "mma.sync.aligned.m16n8k16.row.col.f32.f16.f16.f32 "
        "{%0,%1,%2,%3},{%4,%5,%6,%7},{%8,%9},{%0,%1,%2,%3};"
        : "+f"(c[0]), "+f"(c[1]), "+f"(c[2]), "+f"(c[3])
        : "r"(a[0]), "r"(a[1]), "r"(a[2]), "r"(a[3]), "r"(b[0]), "r"(b[1]));
}

__device__ __forceinline__ uint32_t smem_u32(const void* p) {
    return (uint32_t)__cvta_generic_to_shared(p);
}
__device__ __forceinline__ void cp16(uint32_t dst, const void* src) {
    asm volatile("cp.async.cg.shared.global [%0], [%1], 16;" :: "r"(dst), "l"(src));
}
__device__ __forceinline__ void cp4(uint32_t dst, const void* src) {
    asm volatile("cp.async.ca.shared.global [%0], [%1], 4;" :: "r"(dst), "l"(src));
}

// ---------------------------------------------------------------------------
// K0: convert+transpose W1 (12 blocks) and msg_w2 (3 blocks) to fp16 [n][k].
// ---------------------------------------------------------------------------
__global__ void prep_weights_kernel(const float* __restrict__ gate_w1,
                                    const float* __restrict__ msg_w1,
                                    const float* __restrict__ msg_w2)
{
    const int z = blockIdx.x;
    if (z < 12) {
        const int h = z >> 2;
        const int kind = z & 3;
        const float* W;
        if (kind == 0)      W = gate_w1 + (size_t)h*128*128;
        else if (kind == 1) W = msg_w1  + (size_t)h*128*128;
        else if (kind == 2) W = gate_w1 + (size_t)h*128*128 + 64*128;
        else                W = msg_w1  + (size_t)h*128*128 + 64*128;

        __half* dst = g_wt + (size_t)z * 8192;
        for (int i = threadIdx.x; i < 8192; i += 256) {
            const int n = i >> 6;
            const int k = i & 63;
            dst[i] = __float2half(W[(size_t)k * 128 + n]);
        }
    } else {
        const int h = z - 12;
        const float* W = msg_w2 + (size_t)h * 128 * 64;   // [k][n], k 0..127, n 0..63
        __half* dst = g_wt2 + (size_t)h * 8192;           // [n][k]
        for (int i = threadIdx.x; i < 8192; i += 256) {
            const int n = i >> 7;
            const int k = i & 127;
            dst[i] = __float2half(W[(size_t)k * 64 + n]);
        }
    }
}

// ---------------------------------------------------------------------------
// K1: fused node precompute, pair-fused epilogue (full-row uint4 copyout).
// Dynamic smem: As 18432 + Bst 18432 + stage 67584 = 104448 B.
// ---------------------------------------------------------------------------
#define NG_SMEM (18432 + 18432 + 67584)

__global__ void __launch_bounds__(256, 2)
node_gemm_kernel(const float* __restrict__ X,
                 const float* __restrict__ gate_b1,
                 const float* __restrict__ msg_b1)
{
    extern __shared__ __align__(16) unsigned char dynsmem[];
    __half (*As)[72]     = (__half(*)[72])(dynsmem);            // 128 x 72
    __half (*Bst)[72]    = (__half(*)[72])(dynsmem + 18432);    // 128 x 72
    __half (*stage)[264] = (__half(*)[264])(dynsmem + 36864);   // 128 x 264

    const int tid  = threadIdx.x;     // 256 threads, 8 warps
    const int wid  = tid >> 5;
    const int lane = tid & 31;
    const int gid  = lane >> 2;       // 0..7
    const int tig  = lane & 3;        // 0..3
    const int warp_m = wid & 3;       // 4 warps over 128 rows
    const int warp_n = wid >> 2;      // 2 warps over 128 cols (64 each)
    const int n0 = blockIdx.x * 128;
    const int cb_w = warp_n * 64;

    // Load X tile 128x64 fp32 -> fp16 smem (once)
    #pragma unroll
    for (int it = 0; it < 8; it++) {
        const int f4 = tid + it * 256;         // 0..2047 float4s
        const int node = f4 >> 4;
        const int c4 = (f4 & 15) * 4;
        float4 v = *(const float4*)(X + (size_t)(n0 + node) * 64 + c4);
        *(__half2*)&As[node][c4]     = __floats2half2_rn(v.x, v.y);
        *(__half2*)&As[node][c4 + 2] = __floats2half2_rn(v.z, v.w);
    }

    for (int pair = 0; pair < 6; pair++) {
        const int h = pair >> 1;
        const int t = pair & 1;                 // 0 = self, 1 = nbr
        __half* table = t ? g_nbr_h : g_self_h;

        #pragma unroll
        for (int sub = 0; sub < 2; sub++) {     // 0 = gate, 1 = msg
            const int z = h * 4 + t * 2 + sub;
            const float* bias = nullptr;
            if (t == 0) bias = (sub == 0) ? gate_b1 + h * 128 : msg_b1 + h * 128;

            __syncthreads();   // prev MMA reads of Bst done; prev copyout of stage done
            // Fill Bst (vectorized: 1024 uint4s)
            {
                const __half* src = g_wt + (size_t)z * 8192;
                #pragma unroll
                for (int it = 0; it < 4; it++) {
                    const int idx = tid + it * 256;    // 0..1023
                    const int nn = idx >> 3;
                    const int k8 = (idx & 7) * 8;
                    *(uint4*)&Bst[nn][k8] = *(const uint4*)(src + nn * 64 + k8);
                }
            }
            __syncthreads();

            float acc[2][8][4];
            #pragma unroll
            for (int m = 0; m < 2; m++)
                #pragma unroll
                for (int n = 0; n < 8; n++)
                    #pragma unroll
                    for (int j = 0; j < 4; j++) acc[m][n][j] = 0.f;

            #pragma unroll
            for (int ks = 0; ks < 4; ks++) {
                const int k0 = ks * 16;
                uint32_t a[2][4];
                #pragma unroll
                for (int m = 0; m < 2; m++) {
                    const int rb = warp_m * 32 + m * 16;
                    a[m][0] = *(const uint32_t*)&As[rb + gid    ][k0 + tig * 2];
                    a[m][1] = *(const uint32_t*)&As[rb + gid + 8][k0 + tig * 2];
                    a[m][2] = *(const uint32_t*)&As[rb + gid    ][k0 + 8 + tig * 2];
                    a[m][3] = *(const uint32_t*)&As[rb + gid + 8][k0 + 8 + tig * 2];
                }
                uint32_t b[8][2];
                #pragma unroll
                for (int n = 0; n < 8; n++) {
                    const int col = cb_w + n * 8 + gid;
                    b[n][0] = *(const uint32_t*)&Bst[col][k0 + tig * 2];
                    b[n][1] = *(const uint32_t*)&Bst[col][k0 + 8 + tig * 2];
                }
                #pragma unroll
                for (int m = 0; m < 2; m++)
                    #pragma unroll
                    for (int n = 0; n < 8; n++)
                        mma_f16(acc[m][n], a[m], b[n]);
            }

            // Stage acc (+bias) at interleaved offsets:
            // col c, sub s -> (c>>2)*8 + (c&3) + 4s
            #pragma unroll
            for (int m = 0; m < 2; m++) {
                #pragma unroll
                for (int hr = 0; hr < 2; hr++) {
                    const int row = warp_m * 32 + m * 16 + gid + hr * 8;
                    #pragma unroll
                    for (int n = 0; n < 8; n++) {
                        const int col = cb_w + n * 8 + 2 * tig;
                        float v0 = acc[m][n][hr * 2 + 0];
                        float v1 = acc[m][n][hr * 2 + 1];
                        if (bias) { v0 += bias[col]; v1 += bias[col + 1]; }
                        const int off = (col >> 2) * 8 + (col & 3) + sub * 4;
                        *(__half2*)&stage[row][off] = __floats2half2_rn(v0, v1);
                    }
                }
            }
        }

        __syncthreads();   // stage complete (both subs)
        // Copy out: full 512B rows (8x uint4 per row)
        #pragma unroll
        for (int it = 0; it < 16; it++) {
            const int idx = tid + it * 256;    // 0..4095
            const int r  = idx >> 5;
            const int c8 = (idx & 31) * 8;
            __half* gdst = table + ((size_t)(n0 + r) * 3 + h) * 256 + c8;
            *(uint4*)gdst = *(const uint4*)&stage[r][c8];
        }
    }
}

// ---------------------------------------------------------------------------
// CSR row pointers from sorted self_fea_idx; also resets the work counter.
// ---------------------------------------------------------------------------
__global__ void rowptr_kernel(const int* __restrict__ self_idx)
{
    const int e = blockIdx.x * blockDim.x + threadIdx.x;
    if (e >= M_EDGES) return;
    if (e == 0) g_work = 0u;
    const int s = self_idx[e];
    const int prev = (e == 0) ? -1 : self_idx[e - 1];
    for (int n = prev + 1; n <= s; n++) g_rowptr[n] = e;
    if (e == M_EDGES - 1)
        for (int n = s + 1; n <= N_NODES; n++) g_rowptr[n] = M_EDGES;
}

// ---------------------------------------------------------------------------
// K2: fused softmax + weighted hidden accumulation.
// Persistent warps + batched work-stealing (atomicAdd, 4 nodes per grab).
// 3 heads fused, cp.async smem ring (EDEPTH=3). EGRID = 148 SMs x 6 CTAs
// (exactly one resident wave; late-launching extra CTAs added tail).
// ---------------------------------------------------------------------------
#define EDEPTH 3
#define SLOT_BYTES 1552   // 16B header (w at +0) + 3 heads x 512B
#define EGRID 888

__global__ void __launch_bounds__(128, 6)
edge_kernel(const int* __restrict__ nbr_idx,
            const float* __restrict__ elem_weights,
            const float* __restrict__ gate_w2,
            const float* __restrict__ gate_b2)
{
    __shared__ __align__(16) unsigned char buf[4][EDEPTH][SLOT_BYTES];

    const int wslot = threadIdx.x >> 5;
    const int lane  = threadIdx.x & 31;

    // Node-invariant per-head gate vectors
    float w2v[3][4], b2[3];
    #pragma unroll
    for (int h = 0; h < 3; h++) {
        const float4 wv = *(const float4*)(gate_w2 + h * 128 + lane * 4);
        w2v[h][0] = wv.x; w2v[h][1] = wv.y; w2v[h][2] = wv.z; w2v[h][3] = wv.w;
        b2[h] = gate_b2[h];
    }

    const uint32_t sbase = smem_u32(&buf[wslot][0][0]);

    for (;;) {
        int base;
        if (lane == 0) base = (int)atomicAdd(&g_work, 4u);
        base = __shfl_sync(0xffffffffu, base, 0);
        if (base >= N_NODES) return;
        const int nend = (base + 4 < N_NODES) ? base + 4 : N_NODES;

        for (int n = base; n < nend; n++) {
            // Self chunks per head
            float sg[3][4], sm[3][4];
            #pragma unroll
            for (int h = 0; h < 3; h++) {
                const uint4 u = *(const uint4*)(g_self_h + ((size_t)n * 3 + h) * 256 + lane * 8);
                const float2 a0 = __half22float2(*(__half2*)&u.x);
                const float2 a1 = __half22float2(*(__half2*)&u.y);
                const float2 a2 = __half22float2(*(__half2*)&u.z);
                const float2 a3 = __half22float2(*(__half2*)&u.w);
                sg[h][0] = a0.x; sg[h][1] = a0.y; sg[h][2] = a1.x; sg[h][3] = a1.y;
                sm[h][0] = a2.x; sm[h][1] = a2.y; sm[h][2] = a3.x; sm[h][3] = a3.y;
            }

            const int e0 = g_rowptr[n];
            const int e1 = g_rowptr[n + 1];
            const int deg = e1 - e0;

            // Prologue: prefetch first EDEPTH edges
            #pragma unroll
            for (int d = 0; d < EDEPTH; d++) {
                if (d < deg) {
                    const int j = __ldg(&nbr_idx[e0 + d]);
                    const uint32_t sb = sbase + d * SLOT_BYTES;
                    const __half* src = g_nbr_h + (size_t)j * 768 + lane * 8;
                    const uint32_t dd = sb + 16 + lane * 16;
                    cp16(dd,        src);
                    cp16(dd + 512,  src + 256);
                    cp16(dd + 1024, src + 512);
                    if (lane == 0) cp4(sb, elem_weights + j);
                }
                asm volatile("cp.async.commit_group;" ::: "memory");
            }
            int jn = 0;
            if (EDEPTH < deg) jn = __ldg(&nbr_idx[e0 + EDEPTH]);

            float acc[3][4];
            float denom[3] = {0.f, 0.f, 0.f};
            #pragma unroll
            for (int h = 0; h < 3; h++)
                #pragma unroll
                for (int d = 0; d < 4; d++) acc[h][d] = 0.f;

            int slot = 0;
            for (int i = 0; i < deg; i++) {
                asm volatile("cp.async.wait_group %0;" :: "n"(EDEPTH - 1) : "memory");
                __syncwarp();

                const unsigned char* sp = &buf[wslot][slot][0];
                const float w = *(const float*)sp;
                uint4 u[3];
                #pragma unroll
                for (int h = 0; h < 3; h++)
                    u[h] = *(const uint4*)(sp + 16 + h * 512 + lane * 16);

                const int ipf = i + EDEPTH;
                if (ipf < deg) {
                    const uint32_t sb = sbase + slot * SLOT_BYTES;
                    const __half* src = g_nbr_h + (size_t)jn * 768 + lane * 8;
                    const uint32_t dd = sb + 16 + lane * 16;
                    cp16(dd,        src);
                    cp16(dd + 512,  src + 256);
                    cp16(dd + 1024, src + 512);
                    if (lane == 0) cp4(sb, elem_weights + jn);
                    if (ipf + 1 < deg) jn = __ldg(&nbr_idx[e0 + ipf + 1]);
                }
                asm volatile("cp.async.commit_group;" ::: "memory");

                float p[3], nm[3][4];
                #pragma unroll
                for (int h = 0; h < 3; h++) {
                    const float2 a0 = __half22float2(*(__half2*)&u[h].x);
                    const float2 a1 = __half22float2(*(__half2*)&u[h].y);
                    const float2 a2 = __half22float2(*(__half2*)&u[h].z);
                    const float2 a3 = __half22float2(*(__half2*)&u[h].w);
                    p[h] = lk(sg[h][0] + a0.x) * w2v[h][0]
                         + lk(sg[h][1] + a0.y) * w2v[h][1]
                         + lk(sg[h][2] + a1.x) * w2v[h][2]
                         + lk(sg[h][3] + a1.y) * w2v[h][3];
                    nm[h][0] = a2.x; nm[h][1] = a2.y; nm[h][2] = a3.x; nm[h][3] = a3.y;
                }
                #pragma unroll
                for (int s = 16; s >= 1; s >>= 1) {
                    p[0] += __shfl_xor_sync(0xffffffffu, p[0], s);
                    p[1] += __shfl_xor_sync(0xffffffffu, p[1], s);
                    p[2] += __shfl_xor_sync(0xffffffffu, p[2], s);
                }
                #pragma unroll
                for (int h = 0; h < 3; h++) {
                    const float ev = w * __expf(p[h] + b2[h]);
                    denom[h] += ev;
                    acc[h][0] += ev * lk(sm[h][0] + nm[h][0]);
                    acc[h][1] += ev * lk(sm[h][1] + nm[h][1]);
                    acc[h][2] += ev * lk(sm[h][2] + nm[h][2]);
                    acc[h][3] += ev * lk(sm[h][3] + nm[h][3]);
                }

                slot = (slot + 1 == EDEPTH) ? 0 : slot + 1;
            }

            #pragma unroll
            for (int h = 0; h < 3; h++) {
                const float inv = 1.f / (denom[h] + 1e-10f);
                __half2 h0 = __floats2half2_rn(acc[h][0] * inv, acc[h][1] * inv);
                __half2 h1 = __floats2half2_rn(acc[h][2] * inv, acc[h][3] * inv);
                uint2 uo;
                uo.x = *(uint32_t*)&h0;
                uo.y = *(uint32_t*)&h1;
                *(uint2*)(g_acc_h + ((size_t)h * N_NODES + n) * 128 + lane * 4) = uo;
                if (lane == 0) g_sattn[(size_t)h * N_NODES + n] = denom[h] * inv;
            }
        }
    }
}

// ---------------------------------------------------------------------------
// K3: out[n][f] = x[n][f] + (1/3) * sum_h ( acc[h][n] @ msg_w2[h] + sattn[h][n]*msg_b2[h][f] )
// GEMM via fp16 mma.m16n8k16. Restructured for occupancy (R16 post-mortem:
// latency-bound at 2 CTAs/SM): 128-thread blocks, 64-node tiles, pre-transposed
// fp16 msg_w2 (g_wt2) so the B fill is pure uint4 copies.
// ---------------------------------------------------------------------------
__global__ void __launch_bounds__(128, 7)
out_gemm_kernel(const float* __restrict__ msg_b2,
                const float* __restrict__ X,
                float* __restrict__ out)
{
    __shared__ __half As[64][72];    // 64 nodes x 64 k (fp16)
    __shared__ __half Bst[64][72];   // 64 cols x 64 k (fp16, pre-transposed)

    const int tid  = threadIdx.x;    // 128 threads, 4 warps
    const int wid  = tid >> 5;
    const int lane = tid & 31;
    const int gid  = lane >> 2;      // 0..7
    const int tig  = lane & 3;       // 0..3
    const int n0 = blockIdx.x * 64;

    float acc[8][4];
    #pragma unroll
    for (int nt = 0; nt < 8; nt++)
        #pragma unroll
        for (int jj = 0; jj < 4; jj++) acc[nt][jj] = 0.f;

    #pragma unroll
    for (int kc = 0; kc < 6; kc++) {
        const int h = kc >> 1;
        // A tile: 64 nodes x 64 k (512 uint4 over 128 threads)
        const __half* asrc = g_acc_h + ((size_t)h * N_NODES + n0) * 128 + (kc & 1) * 64;
        #pragma unroll
        for (int it = 0; it < 4; it++) {
            const int idx = tid + it * 128;      // 0..511
            const int row = idx >> 3;
            const int c8 = (idx & 7) * 8;
            *(uint4*)&As[row][c8] = *(const uint4*)(asrc + (size_t)row * 128 + c8);
        }
        // B tile: 64 cols x 64 k from pre-transposed g_wt2
        const __half* bsrc = g_wt2 + (size_t)h * 8192 + (kc & 1) * 64;
        #pragma unroll
        for (int it = 0; it < 4; it++) {
            const int idx = tid + it * 128;      // 0..511
            const int col = idx >> 3;
            const int k8 = (idx & 7) * 8;
            *(uint4*)&Bst[col][k8] = *(const uint4*)(bsrc + (size_t)col * 128 + k8);
        }
        __syncthreads();

        #pragma unroll
        for (int ks = 0; ks < 4; ks++) {
            const int k0 = ks * 16;
            uint32_t a[4];
            const int rb = wid * 16;
            a[0] = *(const uint32_t*)&As[rb + gid    ][k0 + tig * 2];
            a[1] = *(const uint32_t*)&As[rb + gid + 8][k0 + tig * 2];
            a[2] = *(const uint32_t*)&As[rb + gid    ][k0 + 8 + tig * 2];
            a[3] = *(const uint32_t*)&As[rb + gid + 8][k0 + 8 + tig * 2];
            uint32_t b[8][2];
            #pragma unroll
            for (int nt = 0; nt < 8; nt++) {
                const int col = nt * 8 + gid;
                b[nt][0] = *(const uint32_t*)&Bst[col][k0 + tig * 2];
                b[nt][1] = *(const uint32_t*)&Bst[col][k0 + 8 + tig * 2];
            }
            #pragma unroll
            for (int nt = 0; nt < 8; nt++)
                mma_f16(acc[nt], a, b[nt]);
        }
        __syncthreads();
    }

    // Epilogue
    const float inv3 = 1.f / 3.f;
    #pragma unroll
    for (int hf = 0; hf < 2; hf++) {
        const int r = n0 + wid * 16 + gid + hf * 8;
        const float s0 = g_sattn[r];
        const float s1 = g_sattn[(size_t)N_NODES + r];
        const float s2 = g_sattn[(size_t)2 * N_NODES + r];
        #pragma unroll
        for (int nt = 0; nt < 8; nt++) {
            const int c = nt * 8 + tig * 2;
            const float bt0 = s0 * msg_b2[c]     + s1 * msg_b2[64 + c]     + s2 * msg_b2[128 + c];
            const float bt1 = s0 * msg_b2[c + 1] + s1 * msg_b2[64 + c + 1] + s2 * msg_b2[128 + c + 1];
            const float2 xv = *(const float2*)(X + (size_t)r * 64 + c);
            float2 o;
            o.x = inv3 * (acc[nt][hf * 2 + 0] + bt0) + xv.x;
            o.y = inv3 * (acc[nt][hf * 2 + 1] + bt1) + xv.y;
            *(float2*)(out + (size_t)r * 64 + c) = o;
        }
    }
}

// ---------------------------------------------------------------------------
extern "C" void kernel_launch(void* const* d_in, const int* in_sizes, int n_in,
                              void* d_out, int out_size)
{
    const float* elem_weights = (const float*)d_in[0];
    const float* x            = (const float*)d_in[1];
    const int*   self_idx     = (const int*)  d_in[2];
    const int*   nbr_idx      = (const int*)  d_in[3];
    const float* gate_w1      = (const float*)d_in[4];
    const float* gate_b1      = (const float*)d_in[5];
    const float* gate_w2      = (const float*)d_in[6];
    const float* gate_b2      = (const float*)d_in[7];
    const float* msg_w1       = (const float*)d_in[8];
    const float* msg_b1       = (const float*)d_in[9];
    const float* msg_w2       = (const float*)d_in[10];
    const float* msg_b2       = (const float*)d_in[11];
    float* out = (float*)d_out;

    static bool attr_set = false;
    if (!attr_set) {
        cudaFuncSetAttribute(node_gemm_kernel,
                             cudaFuncAttributeMaxDynamicSharedMemorySize, NG_SMEM);
        attr_set = true;
    }

    prep_weights_kernel<<<15, 256>>>(gate_w1, msg_w1, msg_w2);
    node_gemm_kernel<<<N_NODES / 128, 256, NG_SMEM>>>(x, gate_b1, msg_b1);
    rowptr_kernel<<<M_EDGES / 256, 256>>>(self_idx);
    edge_kernel<<<EGRID, 128>>>(nbr_idx, elem_weights, gate_w2, gate_b2);
    out_gemm_kernel<<<N_NODES / 64, 128>>>(msg_b2, x, out);
}